// round 1
// baseline (speedup 1.0000x reference)
#include <cuda_runtime.h>

// Problem constants
#define N_NODES 20000
#define N_EDGES 320000
#define F_IN    64
#define H_DIM   256
#define S_DIM   32
#define L_DIM   128
#define B_BATCH 16
#define EPSF    1e-9f

// ---------------- device scratch (no allocs allowed) ----------------
__device__ float d_XA[N_NODES * H_DIM];
__device__ float d_XB[N_NODES * H_DIM];
__device__ float d_ACC[N_NODES * H_DIM];
__device__ float d_XLN[N_NODES * H_DIM];
__device__ float d_X2[N_NODES * H_DIM];
__device__ float d_T1[N_NODES * H_DIM];
__device__ float d_LG[N_NODES * S_DIM];
__device__ float d_H2[(size_t)N_EDGES * H_DIM];   // 327 MB edge hidden
__device__ float d_pooled[B_BATCH * S_DIM * H_DIM];
__device__ float d_TO[B_BATCH * S_DIM * H_DIM];
__device__ float d_colsum[S_DIM];
__device__ float d_entsum[1];
__device__ int   d_bstart[B_BATCH + 1];

// ---------------- zero ----------------
__global__ void zero_kernel(float* __restrict__ p, int n) {
    int i = blockIdx.x * blockDim.x + threadIdx.x;
    int st = gridDim.x * blockDim.x;
    for (; i < n; i += st) p[i] = 0.f;
}

// ---------------- generic 64x256 tile GEMM ----------------
// Output width fixed at 256. A is [M,K] (PLAIN) or gathered rows
// relu(XA[dst]+XB[src]+bpre) with K=256 (GATHER).
// Store: PLAIN (optional bias/relu, float4) or SCATTER (atomicAdd to C[dst]).
template<int GATHER, int SCATTER, int RELU_OUT, int ADD_BIAS>
__global__ void __launch_bounds__(256, 2) mlp_gemm(
    const float* __restrict__ A, int M, int K,
    const float* __restrict__ XA, const float* __restrict__ XB,
    const float* __restrict__ bpre,
    const int* __restrict__ gsrc, const int* __restrict__ gdst,
    const float* __restrict__ W, const float* __restrict__ bias,
    float* __restrict__ C)
{
    __shared__ __align__(16) float As[64][68];
    __shared__ int sdst[64];
    __shared__ int ssrc[64];

    const int tid  = threadIdx.x;
    const int row0 = blockIdx.x * 64;
    const int tc = tid & 63;
    const int tr = tid >> 6;
    const int c0 = tc * 4;
    const int r0 = tr * 16;

    if (GATHER || SCATTER) {
        if (tid < 64) {
            int rg = row0 + tid;
            int dv = 0, sv = 0;
            if (rg < M) { dv = gdst[rg]; if (GATHER) sv = gsrc[rg]; }
            sdst[tid] = dv;
            ssrc[tid] = sv;
        }
        __syncthreads();
    }

    float acc[16][4];
#pragma unroll
    for (int i = 0; i < 16; i++)
#pragma unroll
        for (int j = 0; j < 4; j++) acc[i][j] = 0.f;

    for (int kc = 0; kc < K; kc += 64) {
        // stage A tile transposed: As[k][r]
        for (int i = tid; i < 1024; i += 256) {
            int r  = i >> 4;
            int f4 = i & 15;
            int k  = kc + f4 * 4;
            int rg = row0 + r;
            float4 v = make_float4(0.f, 0.f, 0.f, 0.f);
            if (rg < M) {
                if (GATHER) {
                    const float4 va = *reinterpret_cast<const float4*>(&XA[(size_t)sdst[r] * 256 + k]);
                    const float4 vb = *reinterpret_cast<const float4*>(&XB[(size_t)ssrc[r] * 256 + k]);
                    const float4 vc = *reinterpret_cast<const float4*>(&bpre[k]);
                    v.x = fmaxf(va.x + vb.x + vc.x, 0.f);
                    v.y = fmaxf(va.y + vb.y + vc.y, 0.f);
                    v.z = fmaxf(va.z + vb.z + vc.z, 0.f);
                    v.w = fmaxf(va.w + vb.w + vc.w, 0.f);
                } else {
                    v = *reinterpret_cast<const float4*>(&A[(size_t)rg * K + k]);
                }
            }
            As[f4 * 4 + 0][r] = v.x;
            As[f4 * 4 + 1][r] = v.y;
            As[f4 * 4 + 2][r] = v.z;
            As[f4 * 4 + 3][r] = v.w;
        }
        __syncthreads();

#pragma unroll 8
        for (int kk = 0; kk < 64; kk++) {
            const float4 w = *reinterpret_cast<const float4*>(&W[(size_t)(kc + kk) * 256 + c0]);
            float a0[16];
#pragma unroll
            for (int q = 0; q < 4; q++) {
                const float4 av = *reinterpret_cast<const float4*>(&As[kk][r0 + q * 4]);
                a0[q * 4 + 0] = av.x; a0[q * 4 + 1] = av.y;
                a0[q * 4 + 2] = av.z; a0[q * 4 + 3] = av.w;
            }
#pragma unroll
            for (int i = 0; i < 16; i++) {
                acc[i][0] = fmaf(a0[i], w.x, acc[i][0]);
                acc[i][1] = fmaf(a0[i], w.y, acc[i][1]);
                acc[i][2] = fmaf(a0[i], w.z, acc[i][2]);
                acc[i][3] = fmaf(a0[i], w.w, acc[i][3]);
            }
        }
        __syncthreads();
    }

    float4 bv = make_float4(0.f, 0.f, 0.f, 0.f);
    if (ADD_BIAS) bv = *reinterpret_cast<const float4*>(&bias[c0]);
#pragma unroll
    for (int i = 0; i < 16; i++) {
        int rl = r0 + i;
        int rg = row0 + rl;
        if (rg < M) {
            float vx = acc[i][0] + bv.x;
            float vy = acc[i][1] + bv.y;
            float vz = acc[i][2] + bv.z;
            float vw = acc[i][3] + bv.w;
            if (RELU_OUT) {
                vx = fmaxf(vx, 0.f); vy = fmaxf(vy, 0.f);
                vz = fmaxf(vz, 0.f); vw = fmaxf(vw, 0.f);
            }
            if (SCATTER) {
                float* o = &C[(size_t)sdst[rl] * 256 + c0];
                atomicAdd(o + 0, vx);
                atomicAdd(o + 1, vy);
                atomicAdd(o + 2, vz);
                atomicAdd(o + 3, vw);
            } else {
                *reinterpret_cast<float4*>(&C[(size_t)rg * 256 + c0]) =
                    make_float4(vx, vy, vz, vw);
            }
        }
    }
}

// ---------------- relu + layernorm (one warp per node, 256 features) ----------------
__global__ void relu_ln_kernel(const float* __restrict__ IN, const float* __restrict__ g,
                               const float* __restrict__ b, float* __restrict__ OUT)
{
    int gid = blockIdx.x * blockDim.x + threadIdx.x;
    int node = gid >> 5;
    int lane = gid & 31;
    if (node >= N_NODES) return;
    const float* x = &IN[(size_t)node * 256];
    float v[8];
    float s = 0.f;
#pragma unroll
    for (int q = 0; q < 2; q++) {
        float4 t = *reinterpret_cast<const float4*>(&x[lane * 8 + q * 4]);
        v[q * 4 + 0] = fmaxf(t.x, 0.f);
        v[q * 4 + 1] = fmaxf(t.y, 0.f);
        v[q * 4 + 2] = fmaxf(t.z, 0.f);
        v[q * 4 + 3] = fmaxf(t.w, 0.f);
    }
#pragma unroll
    for (int i = 0; i < 8; i++) s += v[i];
#pragma unroll
    for (int o = 16; o > 0; o >>= 1) s += __shfl_xor_sync(0xffffffffu, s, o);
    float mu = s * (1.f / 256.f);
    float vs = 0.f;
#pragma unroll
    for (int i = 0; i < 8; i++) { float d = v[i] - mu; vs += d * d; }
#pragma unroll
    for (int o = 16; o > 0; o >>= 1) vs += __shfl_xor_sync(0xffffffffu, vs, o);
    float inv = rsqrtf(vs * (1.f / 256.f) + 1e-5f);
#pragma unroll
    for (int i = 0; i < 8; i++) {
        int c = lane * 8 + i;
        OUT[(size_t)node * 256 + c] = (v[i] - mu) * inv * g[c] + b[c];
    }
}

// ---------------- logits = T1 @ aw2 + ab2 (N x 32) ----------------
__global__ void logits_kernel(const float* __restrict__ T1, const float* __restrict__ aw2,
                              const float* __restrict__ ab2, float* __restrict__ LG)
{
    int c = threadIdx.x;              // 0..31
    int n = blockIdx.x * blockDim.y + threadIdx.y;
    if (n >= N_NODES) return;
    const float* t = &T1[(size_t)n * 256];
    float acc = ab2[c];
#pragma unroll 8
    for (int k = 0; k < 256; k++) acc = fmaf(t[k], aw2[k * 32 + c], acc);
    LG[n * 32 + c] = acc;
}

// ---------------- gumbel softmax + loss partials (warp per node) ----------------
__global__ void gumbel_kernel(const float* __restrict__ LG, const float* __restrict__ U,
                              float* __restrict__ sOut, float* __restrict__ colsum,
                              float* __restrict__ entsum)
{
    int lane = threadIdx.x & 31;
    int gw = (blockIdx.x * blockDim.x + threadIdx.x) >> 5;
    int nw = (gridDim.x * blockDim.x) >> 5;
    float colAcc = 0.f, entAcc = 0.f;
    for (int n = gw; n < N_NODES; n += nw) {
        float u = U[n * 32 + lane];
        float gn = -logf(-logf(u + EPSF) + EPSF);
        float v = LG[n * 32 + lane] + gn;  // tau = 1
        float mx = v;
#pragma unroll
        for (int o = 16; o > 0; o >>= 1) mx = fmaxf(mx, __shfl_xor_sync(0xffffffffu, mx, o));
        float e = expf(v - mx);
        float ssum = e;
#pragma unroll
        for (int o = 16; o > 0; o >>= 1) ssum += __shfl_xor_sync(0xffffffffu, ssum, o);
        float sv = e / ssum;
        sOut[n * 32 + lane] = sv;
        colAcc += sv;
        entAcc += sv * logf(sv + EPSF);
    }
    atomicAdd(&colsum[lane], colAcc);
#pragma unroll
    for (int o = 16; o > 0; o >>= 1) entAcc += __shfl_xor_sync(0xffffffffu, entAcc, o);
    if (lane == 0) atomicAdd(entsum, entAcc);
}

// ---------------- final scalar loss ----------------
__global__ void loss_kernel(const float* __restrict__ colsum, const float* __restrict__ entsum,
                            float* __restrict__ outLoss)
{
    int lane = threadIdx.x;
    float avg = colsum[lane] * (1.f / (float)N_NODES);
    float dv = avg * logf(avg + EPSF);
#pragma unroll
    for (int o = 16; o > 0; o >>= 1) dv += __shfl_xor_sync(0xffffffffu, dv, o);
    if (lane == 0) outLoss[0] = dv - entsum[0] * (1.f / (float)N_NODES);
}

// ---------------- batch segment boundaries (batch is sorted) ----------------
__global__ void bounds_kernel(const int* __restrict__ batch, int* __restrict__ bstart)
{
    int t = threadIdx.x;
    if (t > B_BATCH) return;
    int lo = 0, hi = N_NODES;
    while (lo < hi) {
        int mid = (lo + hi) >> 1;
        if (batch[mid] < t) lo = mid + 1; else hi = mid;
    }
    bstart[t] = lo;
}

// ---------------- pooled[b][k][h] = sum_{n in batch b} s[n][k] * x2[n][h] ----------------
__global__ void pooled_kernel(const float* __restrict__ X2, const float* __restrict__ S,
                              const int* __restrict__ bstart, float* __restrict__ pooled)
{
    int b = blockIdx.x;
    int nchunk = gridDim.y;
    int s0 = bstart[b], s1 = bstart[b + 1];
    int len = s1 - s0;
    int per = (len + nchunk - 1) / nchunk;
    int n0 = s0 + blockIdx.y * per;
    int n1 = min(n0 + per, s1);
    if (n0 >= n1) return;

    int h = threadIdx.x;  // 0..255
    float acc[32];
#pragma unroll
    for (int k = 0; k < 32; k++) acc[k] = 0.f;

    __shared__ float st[8][33];
    for (int base = n0; base < n1; base += 8) {
        __syncthreads();
        {
            int r = threadIdx.x >> 5, c = threadIdx.x & 31;
            st[r][c] = (base + r < n1) ? S[(size_t)(base + r) * 32 + c] : 0.f;
        }
        __syncthreads();
        int cnt = min(8, n1 - base);
        for (int r = 0; r < cnt; r++) {
            float xv = X2[(size_t)(base + r) * 256 + h];
#pragma unroll
            for (int k = 0; k < 32; k++) acc[k] = fmaf(st[r][k], xv, acc[k]);
        }
    }
#pragma unroll
    for (int k = 0; k < 32; k++)
        atomicAdd(&pooled[((size_t)b * 32 + k) * 256 + h], acc[k]);
}

// ---------------- latent = TO @ ow2 + ob2 (512 x 128) ----------------
__global__ void out2_kernel(const float* __restrict__ TO, const float* __restrict__ ow2,
                            const float* __restrict__ ob2, float* __restrict__ out)
{
    int r = blockIdx.x;
    int c = threadIdx.x;  // 0..127
    const float* t = &TO[(size_t)r * 256];
    float acc = ob2[c];
#pragma unroll 8
    for (int k = 0; k < 256; k++) acc = fmaf(t[k], ow2[k * 128 + c], acc);
    out[(size_t)r * 128 + c] = acc;
}

// ---------------- launch ----------------
extern "C" void kernel_launch(void* const* d_in, const int* in_sizes, int n_in,
                              void* d_out, int out_size)
{
    const float* x    = (const float*)d_in[0];
    const float* u    = (const float*)d_in[1];
    const int*   ei   = (const int*)d_in[2];
    const int*   batch= (const int*)d_in[3];
    const float* g1w1 = (const float*)d_in[4];
    const float* g1b1 = (const float*)d_in[5];
    const float* g1w2 = (const float*)d_in[6];
    const float* g1b2 = (const float*)d_in[7];
    const float* g1w3 = (const float*)d_in[8];
    const float* g1b3 = (const float*)d_in[9];
    const float* ln1g = (const float*)d_in[10];
    const float* ln1b = (const float*)d_in[11];
    const float* g2w1 = (const float*)d_in[12];
    const float* g2b1 = (const float*)d_in[13];
    const float* g2w2 = (const float*)d_in[14];
    const float* g2b2 = (const float*)d_in[15];
    const float* g2w3 = (const float*)d_in[16];
    const float* g2b3 = (const float*)d_in[17];
    const float* ln2g = (const float*)d_in[18];
    const float* ln2b = (const float*)d_in[19];
    const float* aw1  = (const float*)d_in[20];
    const float* ab1  = (const float*)d_in[21];
    const float* aw2  = (const float*)d_in[22];
    const float* ab2  = (const float*)d_in[23];
    const float* ow1  = (const float*)d_in[24];
    const float* ob1  = (const float*)d_in[25];
    const float* ow2  = (const float*)d_in[26];
    const float* ob2  = (const float*)d_in[27];

    const int* srcI = ei;
    const int* dstI = ei + N_EDGES;

    float* out        = (float*)d_out;
    float* out_latent = out;                                   // [16,32,128]
    float* out_s      = out + B_BATCH * S_DIM * L_DIM;          // [20000,32]
    float* out_loss   = out_s + (size_t)N_NODES * S_DIM;        // scalar

    float *pXA, *pXB, *pACC, *pXLN, *pX2, *pT1, *pLG, *pH2, *pPooled, *pTO, *pColsum, *pEntsum;
    int* pBstart;
    cudaGetSymbolAddress((void**)&pXA, d_XA);
    cudaGetSymbolAddress((void**)&pXB, d_XB);
    cudaGetSymbolAddress((void**)&pACC, d_ACC);
    cudaGetSymbolAddress((void**)&pXLN, d_XLN);
    cudaGetSymbolAddress((void**)&pX2, d_X2);
    cudaGetSymbolAddress((void**)&pT1, d_T1);
    cudaGetSymbolAddress((void**)&pLG, d_LG);
    cudaGetSymbolAddress((void**)&pH2, d_H2);
    cudaGetSymbolAddress((void**)&pPooled, d_pooled);
    cudaGetSymbolAddress((void**)&pTO, d_TO);
    cudaGetSymbolAddress((void**)&pColsum, d_colsum);
    cudaGetSymbolAddress((void**)&pEntsum, d_entsum);
    cudaGetSymbolAddress((void**)&pBstart, d_bstart);

    const int NB_N = (N_NODES + 63) / 64;   // 313
    const int NB_E = N_EDGES / 64;          // 5000

    // zero accumulators for this launch
    zero_kernel<<<256, 256>>>(pACC, N_NODES * H_DIM);
    zero_kernel<<<1, 32>>>(pColsum, S_DIM);
    zero_kernel<<<1, 32>>>(pEntsum, 1);
    zero_kernel<<<32, 256>>>(pPooled, B_BATCH * S_DIM * H_DIM);

    // ---- layer 1 ----
    mlp_gemm<0,0,0,0><<<NB_N, 256>>>(x, N_NODES, F_IN, nullptr, nullptr, nullptr,
                                     nullptr, nullptr, g1w1, nullptr, pXA);
    mlp_gemm<0,0,0,0><<<NB_N, 256>>>(x, N_NODES, F_IN, nullptr, nullptr, nullptr,
                                     nullptr, nullptr, g1w1 + F_IN * H_DIM, nullptr, pXB);
    mlp_gemm<1,0,1,1><<<NB_E, 256>>>(nullptr, N_EDGES, H_DIM, pXA, pXB, g1b1,
                                     srcI, dstI, g1w2, g1b2, pH2);
    mlp_gemm<0,1,0,1><<<NB_E, 256>>>(pH2, N_EDGES, H_DIM, nullptr, nullptr, nullptr,
                                     nullptr, dstI, g1w3, g1b3, pACC);
    relu_ln_kernel<<<(N_NODES * 32 + 255) / 256, 256>>>(pACC, ln1g, ln1b, pXLN);

    // ---- layer 2 ----
    zero_kernel<<<256, 256>>>(pACC, N_NODES * H_DIM);
    mlp_gemm<0,0,0,0><<<NB_N, 256>>>(pXLN, N_NODES, H_DIM, nullptr, nullptr, nullptr,
                                     nullptr, nullptr, g2w1, nullptr, pXA);
    mlp_gemm<0,0,0,0><<<NB_N, 256>>>(pXLN, N_NODES, H_DIM, nullptr, nullptr, nullptr,
                                     nullptr, nullptr, g2w1 + H_DIM * H_DIM, nullptr, pXB);
    mlp_gemm<1,0,1,1><<<NB_E, 256>>>(nullptr, N_EDGES, H_DIM, pXA, pXB, g2b1,
                                     srcI, dstI, g2w2, g2b2, pH2);
    mlp_gemm<0,1,0,1><<<NB_E, 256>>>(pH2, N_EDGES, H_DIM, nullptr, nullptr, nullptr,
                                     nullptr, dstI, g2w3, g2b3, pACC);
    relu_ln_kernel<<<(N_NODES * 32 + 255) / 256, 256>>>(pACC, ln2g, ln2b, pX2);

    // ---- assignment ----
    mlp_gemm<0,0,1,1><<<NB_N, 256>>>(pX2, N_NODES, H_DIM, nullptr, nullptr, nullptr,
                                     nullptr, nullptr, aw1, ab1, pT1);
    {
        dim3 lb(32, 8);
        logits_kernel<<<(N_NODES + 7) / 8, lb>>>(pT1, aw2, ab2, pLG);
    }
    gumbel_kernel<<<80, 256>>>(pLG, u, out_s, pColsum, pEntsum);
    loss_kernel<<<1, 32>>>(pColsum, pEntsum, out_loss);

    // ---- pooling ----
    bounds_kernel<<<1, 32>>>(batch, pBstart);
    {
        dim3 pg(B_BATCH, 8);
        pooled_kernel<<<pg, 256>>>(pX2, out_s, pBstart, pPooled);
    }

    // ---- output MLP ----
    mlp_gemm<0,0,1,1><<<(B_BATCH * S_DIM + 63) / 64, 256>>>(
        pPooled, B_BATCH * S_DIM, H_DIM, nullptr, nullptr, nullptr,
        nullptr, nullptr, ow1, ob1, pTO);
    out2_kernel<<<B_BATCH * S_DIM, 128>>>(pTO, ow2, ob2, out_latent);
}

// round 2
// speedup vs baseline: 1.4735x; 1.4735x over previous
#include <cuda_runtime.h>

// Problem constants
#define N_NODES 20000
#define N_EDGES 320000
#define F_IN    64
#define H_DIM   256
#define S_DIM   32
#define L_DIM   128
#define B_BATCH 16
#define EPSF    1e-9f

typedef unsigned long long u64;

__device__ __forceinline__ u64 pack2(float a, float b) {
    u64 r;
    asm("mov.b64 %0, {%1, %2};" : "=l"(r) : "r"(__float_as_uint(a)), "r"(__float_as_uint(b)));
    return r;
}
__device__ __forceinline__ void unpack2(float& a, float& b, u64 v) {
    unsigned int x, y;
    asm("mov.b64 {%0, %1}, %2;" : "=r"(x), "=r"(y) : "l"(v));
    a = __uint_as_float(x);
    b = __uint_as_float(y);
}
__device__ __forceinline__ void fma2(u64& d, u64 a, u64 b) {
    asm("fma.rn.f32x2 %0, %1, %2, %0;" : "+l"(d) : "l"(a), "l"(b));
}

// ---------------- device scratch (no allocs allowed) ----------------
__device__ float d_XA[N_NODES * H_DIM];
__device__ float d_XB[N_NODES * H_DIM];
__device__ float d_HS[N_NODES * H_DIM];    // segment-summed edge hidden
__device__ float d_ACC[N_NODES * H_DIM];
__device__ float d_XLN[N_NODES * H_DIM];
__device__ float d_X2[N_NODES * H_DIM];
__device__ float d_T1[N_NODES * H_DIM];
__device__ float d_LG[N_NODES * S_DIM];
__device__ float d_degf[N_NODES];
__device__ float d_pooled[B_BATCH * S_DIM * H_DIM];
__device__ float d_TO[B_BATCH * S_DIM * H_DIM];
__device__ float d_colsum[S_DIM];
__device__ float d_entsum[1];
__device__ int   d_bstart[B_BATCH + 1];

// ---------------- zero ----------------
__global__ void zero_kernel(float* __restrict__ p, int n) {
    int i = blockIdx.x * blockDim.x + threadIdx.x;
    int st = gridDim.x * blockDim.x;
    for (; i < n; i += st) p[i] = 0.f;
}

// ---------------- degree of dst ----------------
__global__ void deg_kernel(const int* __restrict__ dst, float* __restrict__ degf) {
    int i = blockIdx.x * blockDim.x + threadIdx.x;
    int st = gridDim.x * blockDim.x;
    for (; i < N_EDGES; i += st) atomicAdd(&degf[dst[i]], 1.f);
}

// ---------------- generic 64x256 tile GEMM (FFMA2 inner loop) ----------------
// Output width fixed at 256.
// GATHER: A rows are relu(XA[dst]+XB[src]+bpre), K=256.
// SCATTER: epilogue atomicAdd into C[dst] (else plain float4 store).
template<int GATHER, int SCATTER, int RELU_OUT, int ADD_BIAS>
__global__ void __launch_bounds__(256, 2) mlp_gemm(
    const float* __restrict__ A, int M, int K,
    const float* __restrict__ XA, const float* __restrict__ XB,
    const float* __restrict__ bpre,
    const int* __restrict__ gsrc, const int* __restrict__ gdst,
    const float* __restrict__ W, const float* __restrict__ bias,
    float* __restrict__ C)
{
    __shared__ __align__(16) float As[64][68];
    __shared__ int sdst[64];
    __shared__ int ssrc[64];

    const int tid  = threadIdx.x;
    const int row0 = blockIdx.x * 64;
    const int tc = tid & 63;
    const int tr = tid >> 6;
    const int c0 = tc * 4;
    const int r0 = tr * 16;

    if (GATHER || SCATTER) {
        if (tid < 64) {
            int rg = row0 + tid;
            int dv = 0, sv = 0;
            if (rg < M) { dv = gdst[rg]; if (GATHER) sv = gsrc[rg]; }
            sdst[tid] = dv;
            ssrc[tid] = sv;
        }
        __syncthreads();
    }

    // row-pair packed accumulators: acc2[p][j] = cols c0+j of rows (r0+2p, r0+2p+1)
    u64 acc2[8][4];
#pragma unroll
    for (int p = 0; p < 8; p++)
#pragma unroll
        for (int j = 0; j < 4; j++) acc2[p][j] = 0ull;

    for (int kc = 0; kc < K; kc += 64) {
        // stage A tile transposed: As[k][r]
        for (int i = tid; i < 1024; i += 256) {
            int r  = i >> 4;
            int f4 = i & 15;
            int k  = kc + f4 * 4;
            int rg = row0 + r;
            float4 v = make_float4(0.f, 0.f, 0.f, 0.f);
            if (rg < M) {
                if (GATHER) {
                    const float4 va = *reinterpret_cast<const float4*>(&XA[(size_t)sdst[r] * 256 + k]);
                    const float4 vb = *reinterpret_cast<const float4*>(&XB[(size_t)ssrc[r] * 256 + k]);
                    const float4 vc = *reinterpret_cast<const float4*>(&bpre[k]);
                    v.x = fmaxf(va.x + vb.x + vc.x, 0.f);
                    v.y = fmaxf(va.y + vb.y + vc.y, 0.f);
                    v.z = fmaxf(va.z + vb.z + vc.z, 0.f);
                    v.w = fmaxf(va.w + vb.w + vc.w, 0.f);
                } else {
                    v = *reinterpret_cast<const float4*>(&A[(size_t)rg * K + k]);
                }
            }
            As[f4 * 4 + 0][r] = v.x;
            As[f4 * 4 + 1][r] = v.y;
            As[f4 * 4 + 2][r] = v.z;
            As[f4 * 4 + 3][r] = v.w;
        }
        __syncthreads();

#pragma unroll 8
        for (int kk = 0; kk < 64; kk++) {
            const float4 wv = *reinterpret_cast<const float4*>(&W[(size_t)(kc + kk) * 256 + c0]);
            u64 wd[4];
            wd[0] = pack2(wv.x, wv.x);
            wd[1] = pack2(wv.y, wv.y);
            wd[2] = pack2(wv.z, wv.z);
            wd[3] = pack2(wv.w, wv.w);
#pragma unroll
            for (int q = 0; q < 4; q++) {
                ulonglong2 av = *reinterpret_cast<const ulonglong2*>(&As[kk][r0 + q * 4]);
#pragma unroll
                for (int j = 0; j < 4; j++) fma2(acc2[q * 2 + 0][j], av.x, wd[j]);
#pragma unroll
                for (int j = 0; j < 4; j++) fma2(acc2[q * 2 + 1][j], av.y, wd[j]);
            }
        }
        __syncthreads();
    }

    float accf[16][4];
#pragma unroll
    for (int p = 0; p < 8; p++)
#pragma unroll
        for (int j = 0; j < 4; j++)
            unpack2(accf[2 * p][j], accf[2 * p + 1][j], acc2[p][j]);

    float4 bv = make_float4(0.f, 0.f, 0.f, 0.f);
    if (ADD_BIAS) bv = *reinterpret_cast<const float4*>(&bias[c0]);
#pragma unroll
    for (int i = 0; i < 16; i++) {
        int rl = r0 + i;
        int rg = row0 + rl;
        if (rg < M) {
            float vx = accf[i][0] + bv.x;
            float vy = accf[i][1] + bv.y;
            float vz = accf[i][2] + bv.z;
            float vw = accf[i][3] + bv.w;
            if (RELU_OUT) {
                vx = fmaxf(vx, 0.f); vy = fmaxf(vy, 0.f);
                vz = fmaxf(vz, 0.f); vw = fmaxf(vw, 0.f);
            }
            if (SCATTER) {
                float* o = &C[(size_t)sdst[rl] * 256 + c0];
                atomicAdd(o + 0, vx);
                atomicAdd(o + 1, vy);
                atomicAdd(o + 2, vz);
                atomicAdd(o + 3, vw);
            } else {
                *reinterpret_cast<float4*>(&C[(size_t)rg * 256 + c0]) =
                    make_float4(vx, vy, vz, vw);
            }
        }
    }
}

// ---------------- relu + layernorm with optional deg*b3 pre-add ----------------
__global__ void relu_ln_kernel(const float* __restrict__ IN,
                               const float* __restrict__ degf, const float* __restrict__ b3,
                               const float* __restrict__ g, const float* __restrict__ b,
                               float* __restrict__ OUT)
{
    int gid = blockIdx.x * blockDim.x + threadIdx.x;
    int node = gid >> 5;
    int lane = gid & 31;
    if (node >= N_NODES) return;
    const float* x = &IN[(size_t)node * 256];
    float dg = degf[node];
    float v[8];
    float s = 0.f;
#pragma unroll
    for (int q = 0; q < 2; q++) {
        float4 t = *reinterpret_cast<const float4*>(&x[lane * 8 + q * 4]);
        float4 bb = *reinterpret_cast<const float4*>(&b3[lane * 8 + q * 4]);
        v[q * 4 + 0] = fmaxf(fmaf(dg, bb.x, t.x), 0.f);
        v[q * 4 + 1] = fmaxf(fmaf(dg, bb.y, t.y), 0.f);
        v[q * 4 + 2] = fmaxf(fmaf(dg, bb.z, t.z), 0.f);
        v[q * 4 + 3] = fmaxf(fmaf(dg, bb.w, t.w), 0.f);
    }
#pragma unroll
    for (int i = 0; i < 8; i++) s += v[i];
#pragma unroll
    for (int o = 16; o > 0; o >>= 1) s += __shfl_xor_sync(0xffffffffu, s, o);
    float mu = s * (1.f / 256.f);
    float vs = 0.f;
#pragma unroll
    for (int i = 0; i < 8; i++) { float d = v[i] - mu; vs += d * d; }
#pragma unroll
    for (int o = 16; o > 0; o >>= 1) vs += __shfl_xor_sync(0xffffffffu, vs, o);
    float inv = rsqrtf(vs * (1.f / 256.f) + 1e-5f);
#pragma unroll
    for (int i = 0; i < 8; i++) {
        int c = lane * 8 + i;
        OUT[(size_t)node * 256 + c] = (v[i] - mu) * inv * g[c] + b[c];
    }
}

// ---------------- logits = T1 @ aw2 + ab2 (N x 32) ----------------
__global__ void logits_kernel(const float* __restrict__ T1, const float* __restrict__ aw2,
                              const float* __restrict__ ab2, float* __restrict__ LG)
{
    int c = threadIdx.x;              // 0..31
    int n = blockIdx.x * blockDim.y + threadIdx.y;
    if (n >= N_NODES) return;
    const float* t = &T1[(size_t)n * 256];
    float acc = ab2[c];
#pragma unroll 8
    for (int k = 0; k < 256; k++) acc = fmaf(t[k], aw2[k * 32 + c], acc);
    LG[n * 32 + c] = acc;
}

// ---------------- gumbel softmax + loss partials (warp per node) ----------------
__global__ void gumbel_kernel(const float* __restrict__ LG, const float* __restrict__ U,
                              float* __restrict__ sOut, float* __restrict__ colsum,
                              float* __restrict__ entsum)
{
    int lane = threadIdx.x & 31;
    int gw = (blockIdx.x * blockDim.x + threadIdx.x) >> 5;
    int nw = (gridDim.x * blockDim.x) >> 5;
    float colAcc = 0.f, entAcc = 0.f;
    for (int n = gw; n < N_NODES; n += nw) {
        float u = U[n * 32 + lane];
        float gn = -logf(-logf(u + EPSF) + EPSF);
        float v = LG[n * 32 + lane] + gn;  // tau = 1
        float mx = v;
#pragma unroll
        for (int o = 16; o > 0; o >>= 1) mx = fmaxf(mx, __shfl_xor_sync(0xffffffffu, mx, o));
        float e = expf(v - mx);
        float ssum = e;
#pragma unroll
        for (int o = 16; o > 0; o >>= 1) ssum += __shfl_xor_sync(0xffffffffu, ssum, o);
        float sv = e / ssum;
        sOut[n * 32 + lane] = sv;
        colAcc += sv;
        entAcc += sv * logf(sv + EPSF);
    }
    atomicAdd(&colsum[lane], colAcc);
#pragma unroll
    for (int o = 16; o > 0; o >>= 1) entAcc += __shfl_xor_sync(0xffffffffu, entAcc, o);
    if (lane == 0) atomicAdd(entsum, entAcc);
}

// ---------------- final scalar loss ----------------
__global__ void loss_kernel(const float* __restrict__ colsum, const float* __restrict__ entsum,
                            float* __restrict__ outLoss)
{
    int lane = threadIdx.x;
    float avg = colsum[lane] * (1.f / (float)N_NODES);
    float dv = avg * logf(avg + EPSF);
#pragma unroll
    for (int o = 16; o > 0; o >>= 1) dv += __shfl_xor_sync(0xffffffffu, dv, o);
    if (lane == 0) outLoss[0] = dv - entsum[0] * (1.f / (float)N_NODES);
}

// ---------------- batch segment boundaries (batch is sorted) ----------------
__global__ void bounds_kernel(const int* __restrict__ batch, int* __restrict__ bstart)
{
    int t = threadIdx.x;
    if (t > B_BATCH) return;
    int lo = 0, hi = N_NODES;
    while (lo < hi) {
        int mid = (lo + hi) >> 1;
        if (batch[mid] < t) lo = mid + 1; else hi = mid;
    }
    bstart[t] = lo;
}

// ---------------- pooled[b][k][h] = sum_{n in batch b} s[n][k] * x2[n][h] ----------------
__global__ void pooled_kernel(const float* __restrict__ X2, const float* __restrict__ S,
                              const int* __restrict__ bstart, float* __restrict__ pooled)
{
    int b = blockIdx.x;
    int nchunk = gridDim.y;
    int s0 = bstart[b], s1 = bstart[b + 1];
    int len = s1 - s0;
    int per = (len + nchunk - 1) / nchunk;
    int n0 = s0 + blockIdx.y * per;
    int n1 = min(n0 + per, s1);
    if (n0 >= n1) return;

    int h = threadIdx.x;  // 0..255
    float acc[32];
#pragma unroll
    for (int k = 0; k < 32; k++) acc[k] = 0.f;

    __shared__ float st[8][33];
    for (int base = n0; base < n1; base += 8) {
        __syncthreads();
        {
            int r = threadIdx.x >> 5, c = threadIdx.x & 31;
            st[r][c] = (base + r < n1) ? S[(size_t)(base + r) * 32 + c] : 0.f;
        }
        __syncthreads();
        int cnt = min(8, n1 - base);
        for (int r = 0; r < cnt; r++) {
            float xv = X2[(size_t)(base + r) * 256 + h];
#pragma unroll
            for (int k = 0; k < 32; k++) acc[k] = fmaf(st[r][k], xv, acc[k]);
        }
    }
#pragma unroll
    for (int k = 0; k < 32; k++)
        atomicAdd(&pooled[((size_t)b * 32 + k) * 256 + h], acc[k]);
}

// ---------------- latent = TO @ ow2 + ob2 (512 x 128) ----------------
__global__ void out2_kernel(const float* __restrict__ TO, const float* __restrict__ ow2,
                            const float* __restrict__ ob2, float* __restrict__ out)
{
    int r = blockIdx.x;
    int c = threadIdx.x;  // 0..127
    const float* t = &TO[(size_t)r * 256];
    float acc = ob2[c];
#pragma unroll 8
    for (int k = 0; k < 256; k++) acc = fmaf(t[k], ow2[k * 128 + c], acc);
    out[(size_t)r * 128 + c] = acc;
}

// ---------------- launch ----------------
extern "C" void kernel_launch(void* const* d_in, const int* in_sizes, int n_in,
                              void* d_out, int out_size)
{
    const float* x    = (const float*)d_in[0];
    const float* u    = (const float*)d_in[1];
    const int*   ei   = (const int*)d_in[2];
    const int*   batch= (const int*)d_in[3];
    const float* g1w1 = (const float*)d_in[4];
    const float* g1b1 = (const float*)d_in[5];
    const float* g1w2 = (const float*)d_in[6];
    const float* g1b2 = (const float*)d_in[7];
    const float* g1w3 = (const float*)d_in[8];
    const float* g1b3 = (const float*)d_in[9];
    const float* ln1g = (const float*)d_in[10];
    const float* ln1b = (const float*)d_in[11];
    const float* g2w1 = (const float*)d_in[12];
    const float* g2b1 = (const float*)d_in[13];
    const float* g2w2 = (const float*)d_in[14];
    const float* g2b2 = (const float*)d_in[15];
    const float* g2w3 = (const float*)d_in[16];
    const float* g2b3 = (const float*)d_in[17];
    const float* ln2g = (const float*)d_in[18];
    const float* ln2b = (const float*)d_in[19];
    const float* aw1  = (const float*)d_in[20];
    const float* ab1  = (const float*)d_in[21];
    const float* aw2  = (const float*)d_in[22];
    const float* ab2  = (const float*)d_in[23];
    const float* ow1  = (const float*)d_in[24];
    const float* ob1  = (const float*)d_in[25];
    const float* ow2  = (const float*)d_in[26];
    const float* ob2  = (const float*)d_in[27];

    const int* srcI = ei;
    const int* dstI = ei + N_EDGES;

    float* out        = (float*)d_out;
    float* out_latent = out;                                   // [16,32,128]
    float* out_s      = out + B_BATCH * S_DIM * L_DIM;          // [20000,32]
    float* out_loss   = out_s + (size_t)N_NODES * S_DIM;        // scalar

    float *pXA, *pXB, *pHS, *pACC, *pXLN, *pX2, *pT1, *pLG, *pDeg, *pPooled, *pTO, *pColsum, *pEntsum;
    int* pBstart;
    cudaGetSymbolAddress((void**)&pXA, d_XA);
    cudaGetSymbolAddress((void**)&pXB, d_XB);
    cudaGetSymbolAddress((void**)&pHS, d_HS);
    cudaGetSymbolAddress((void**)&pACC, d_ACC);
    cudaGetSymbolAddress((void**)&pXLN, d_XLN);
    cudaGetSymbolAddress((void**)&pX2, d_X2);
    cudaGetSymbolAddress((void**)&pT1, d_T1);
    cudaGetSymbolAddress((void**)&pLG, d_LG);
    cudaGetSymbolAddress((void**)&pDeg, d_degf);
    cudaGetSymbolAddress((void**)&pPooled, d_pooled);
    cudaGetSymbolAddress((void**)&pTO, d_TO);
    cudaGetSymbolAddress((void**)&pColsum, d_colsum);
    cudaGetSymbolAddress((void**)&pEntsum, d_entsum);
    cudaGetSymbolAddress((void**)&pBstart, d_bstart);

    const int NB_N = (N_NODES + 63) / 64;   // 313
    const int NB_E = N_EDGES / 64;          // 5000

    // zero accumulators for this launch
    zero_kernel<<<128, 256>>>(pDeg, N_NODES);
    zero_kernel<<<256, 256>>>(pHS, N_NODES * H_DIM);
    zero_kernel<<<1, 32>>>(pColsum, S_DIM);
    zero_kernel<<<1, 32>>>(pEntsum, 1);
    zero_kernel<<<32, 256>>>(pPooled, B_BATCH * S_DIM * H_DIM);
    deg_kernel<<<256, 256>>>(dstI, pDeg);

    // ---- layer 1 ----
    mlp_gemm<0,0,0,0><<<NB_N, 256>>>(x, N_NODES, F_IN, nullptr, nullptr, nullptr,
                                     nullptr, nullptr, g1w1, nullptr, pXA);
    mlp_gemm<0,0,0,0><<<NB_N, 256>>>(x, N_NODES, F_IN, nullptr, nullptr, nullptr,
                                     nullptr, nullptr, g1w1 + F_IN * H_DIM, nullptr, pXB);
    // fused: HS[dst] += relu( relu(XA[dst]+XB[src]+b1) @ w2 + b2 )
    mlp_gemm<1,1,1,1><<<NB_E, 256>>>(nullptr, N_EDGES, H_DIM, pXA, pXB, g1b1,
                                     srcI, dstI, g1w2, g1b2, pHS);
    // ACC = HS @ w3  (b3 folded in via deg in relu_ln)
    mlp_gemm<0,0,0,0><<<NB_N, 256>>>(pHS, N_NODES, H_DIM, nullptr, nullptr, nullptr,
                                     nullptr, nullptr, g1w3, nullptr, pACC);
    relu_ln_kernel<<<(N_NODES * 32 + 255) / 256, 256>>>(pACC, pDeg, g1b3, ln1g, ln1b, pXLN);

    // ---- layer 2 ----
    zero_kernel<<<256, 256>>>(pHS, N_NODES * H_DIM);
    mlp_gemm<0,0,0,0><<<NB_N, 256>>>(pXLN, N_NODES, H_DIM, nullptr, nullptr, nullptr,
                                     nullptr, nullptr, g2w1, nullptr, pXA);
    mlp_gemm<0,0,0,0><<<NB_N, 256>>>(pXLN, N_NODES, H_DIM, nullptr, nullptr, nullptr,
                                     nullptr, nullptr, g2w1 + H_DIM * H_DIM, nullptr, pXB);
    mlp_gemm<1,1,1,1><<<NB_E, 256>>>(nullptr, N_EDGES, H_DIM, pXA, pXB, g2b1,
                                     srcI, dstI, g2w2, g2b2, pHS);
    mlp_gemm<0,0,0,0><<<NB_N, 256>>>(pHS, N_NODES, H_DIM, nullptr, nullptr, nullptr,
                                     nullptr, nullptr, g2w3, nullptr, pACC);
    relu_ln_kernel<<<(N_NODES * 32 + 255) / 256, 256>>>(pACC, pDeg, g2b3, ln2g, ln2b, pX2);

    // ---- assignment ----
    mlp_gemm<0,0,1,1><<<NB_N, 256>>>(pX2, N_NODES, H_DIM, nullptr, nullptr, nullptr,
                                     nullptr, nullptr, aw1, ab1, pT1);
    {
        dim3 lb(32, 8);
        logits_kernel<<<(N_NODES + 7) / 8, lb>>>(pT1, aw2, ab2, pLG);
    }
    gumbel_kernel<<<80, 256>>>(pLG, u, out_s, pColsum, pEntsum);
    loss_kernel<<<1, 32>>>(pColsum, pEntsum, out_loss);

    // ---- pooling ----
    bounds_kernel<<<1, 32>>>(batch, pBstart);
    {
        dim3 pg(B_BATCH, 8);
        pooled_kernel<<<pg, 256>>>(pX2, out_s, pBstart, pPooled);
    }

    // ---- output MLP ----
    mlp_gemm<0,0,1,1><<<(B_BATCH * S_DIM + 63) / 64, 256>>>(
        pPooled, B_BATCH * S_DIM, H_DIM, nullptr, nullptr, nullptr,
        nullptr, nullptr, ow1, ob1, pTO);
    out2_kernel<<<B_BATCH * S_DIM, 128>>>(pTO, ow2, ob2, out_latent);
}

// round 4
// speedup vs baseline: 2.7861x; 1.8909x over previous
#include <cuda_runtime.h>
#include <cstdint>

// Problem constants
#define N_NODES 20000
#define N_EDGES 320000
#define F_IN    64
#define H_DIM   256
#define S_DIM   32
#define L_DIM   128
#define B_BATCH 16
#define EPSF    1e-9f

// ===================== helpers =====================
__device__ __forceinline__ uint32_t smem_u32(const void* p) {
    uint32_t a;
    asm("{ .reg .u64 t; cvta.to.shared.u64 t, %1; cvt.u32.u64 %0, t; }" : "=r"(a) : "l"(p));
    return a;
}
__device__ __forceinline__ uint32_t f2tf32(float f) {
    uint32_t r;
    asm("cvt.rna.tf32.f32 %0, %1;" : "=r"(r) : "f"(f));
    return r;
}
__device__ __forceinline__ void mma8(float* c, const uint32_t* a, uint32_t b0, uint32_t b1) {
    asm volatile(
        "mma.sync.aligned.m16n8k8.row.col.f32.tf32.tf32.f32 "
        "{%0,%1,%2,%3}, {%4,%5,%6,%7}, {%8,%9}, {%0,%1,%2,%3};"
        : "+f"(c[0]), "+f"(c[1]), "+f"(c[2]), "+f"(c[3])
        : "r"(a[0]), "r"(a[1]), "r"(a[2]), "r"(a[3]), "r"(b0), "r"(b1));
}

// ===================== device scratch =====================
__device__ float d_XA[N_NODES * H_DIM];
__device__ float d_XB[N_NODES * H_DIM];
__device__ float d_HS[N_NODES * H_DIM];
__device__ float d_ACC[N_NODES * H_DIM];
__device__ float d_XLN[N_NODES * H_DIM];
__device__ float d_X2[N_NODES * H_DIM];
__device__ float d_T1[N_NODES * H_DIM];
__device__ float d_LG[N_NODES * S_DIM];
__device__ float d_degf[N_NODES];
__device__ float d_pooled[B_BATCH * S_DIM * H_DIM];
__device__ float d_TO[B_BATCH * S_DIM * H_DIM];
__device__ float d_colsum[S_DIM];
__device__ float d_entsum[1];
__device__ int   d_bstart[B_BATCH + 1];
// transposed (and tf32-rounded) weights [N][K]
__device__ float d_WT1a[256 * 64];
__device__ float d_WT1b[256 * 64];
__device__ float d_WT2[256 * 256];
__device__ float d_WT3[256 * 256];
__device__ float d_WT4a[256 * 256];
__device__ float d_WT4b[256 * 256];
__device__ float d_WT5[256 * 256];
__device__ float d_WT6[256 * 256];
__device__ float d_WTA[256 * 256];
__device__ float d_WTO[256 * 256];

// ===================== small kernels =====================
__global__ void zero_kernel(float* __restrict__ p, int n) {
    int i = blockIdx.x * blockDim.x + threadIdx.x;
    int st = gridDim.x * blockDim.x;
    for (; i < n; i += st) p[i] = 0.f;
}

__global__ void deg_kernel(const int* __restrict__ dst, float* __restrict__ degf) {
    int i = blockIdx.x * blockDim.x + threadIdx.x;
    int st = gridDim.x * blockDim.x;
    for (; i < N_EDGES; i += st) atomicAdd(&degf[dst[i]], 1.f);
}

// out[c][r] = tf32_round(in[r][c]); in is [R][C]
__global__ void transpose_kernel(const float* __restrict__ in, float* __restrict__ out,
                                 int R, int C) {
    __shared__ float t[32][33];
    int c0 = blockIdx.x * 32, r0 = blockIdx.y * 32;
    for (int j = threadIdx.y; j < 32; j += 8) {
        int r = r0 + j, c = c0 + threadIdx.x;
        t[j][threadIdx.x] = (r < R && c < C) ? in[(size_t)r * C + c] : 0.f;
    }
    __syncthreads();
    for (int j = threadIdx.y; j < 32; j += 8) {
        int oc = c0 + j, orr = r0 + threadIdx.x;
        if (oc < C && orr < R)
            out[(size_t)oc * R + orr] = __uint_as_float(f2tf32(t[threadIdx.x][j]));
    }
}

// ===================== tf32 mma.sync GEMM =====================
// CTA tile 128(M) x 128(N), grid.y picks the 128-col block. K chunks of 32.
// 8 warps: wm = wid&3 (4 x 32 rows), wn = wid>>2 (2 x 64 cols). Warp tile 32x64.
// GATHER: A row = relu(XA[gdst] + XB[gsrc] + bpre), K=256.
// SCATTER: epilogue atomicAdd into C[gdst] (bias/relu applied per edge first).
// Smem stride 36 floats (36 mod 32 == 4) -> conflict-free mma fragment loads.
#define ASLOT 4608  // 128*36 floats

template<int GATHER, int SCATTER, int RELU_OUT, int ADD_BIAS, int KLEN>
__global__ void __launch_bounds__(256, 2) mma_gemm(
    const float* __restrict__ A, int M,
    const float* __restrict__ XA, const float* __restrict__ XB,
    const float* __restrict__ bpre,
    const int* __restrict__ gsrc, const int* __restrict__ gdst,
    const float* __restrict__ WT,   // [256][KLEN] K-major, tf32-rounded
    const float* __restrict__ bias,
    float* __restrict__ C)
{
    extern __shared__ float sm[];
    float* sA = sm;                    // 2 * ASLOT
    float* sB = sm + 2 * ASLOT;        // 2 * ASLOT
    int* sdst = (int*)(sm + 4 * ASLOT);
    int* ssrc = sdst + 128;

    const int tid  = threadIdx.x;
    const int lane = tid & 31;
    const int wid  = tid >> 5;
    const int wm = wid & 3;
    const int wn = wid >> 2;
    const int lr = lane >> 2;
    const int lc = lane & 3;
    const int row0 = blockIdx.x * 128;
    const int col0 = blockIdx.y * 128;
    constexpr int NCH = KLEN / 32;

    if ((GATHER || SCATTER) && tid < 128) {
        sdst[tid] = gdst[row0 + tid];
        if (GATHER) ssrc[tid] = gsrc[row0 + tid];
    }
    if (GATHER || SCATTER) __syncthreads();

    const int arow = tid >> 1;
    const int akh  = (tid & 1) << 4;
    const int bn   = tid >> 1;
    const int bkh  = (tid & 1) << 4;
    const uint32_t sB_addr = smem_u32(sB);
    const float* WTb = WT + (size_t)(col0 + bn) * KLEN + bkh;

    float4 ra[4], rb4[4];

    // ---- B issue (cp.async, 4x16B per thread) ----
#define ISSUE_B(c, buf)                                                          \
    do {                                                                         \
        uint32_t dstb = sB_addr + (uint32_t)((buf) * ASLOT + bn * 36 + bkh) * 4u;\
        const float* srcb = WTb + (c) * 32;                                      \
        _Pragma("unroll")                                                        \
        for (int i = 0; i < 4; i++)                                              \
            asm volatile("cp.async.ca.shared.global [%0], [%1], 16;" ::          \
                         "r"(dstb + (uint32_t)i * 16u), "l"(srcb + i * 4) : "memory"); \
        asm volatile("cp.async.commit_group;" ::: "memory");                     \
    } while (0)

    // ---- A load to regs ----
#define LOAD_A(c)                                                                \
    do {                                                                         \
        int kg = (c) * 32 + akh;                                                 \
        if (GATHER) {                                                            \
            const float* pa = XA + (size_t)sdst[arow] * 256 + kg;                \
            const float* pb = XB + (size_t)ssrc[arow] * 256 + kg;                \
            _Pragma("unroll")                                                    \
            for (int i = 0; i < 4; i++) {                                        \
                ra[i]  = *(const float4*)(pa + 4 * i);                           \
                rb4[i] = *(const float4*)(pb + 4 * i);                           \
            }                                                                    \
        } else {                                                                 \
            int rg = row0 + arow;                                                \
            const float* pa = A + (size_t)rg * KLEN + kg;                        \
            _Pragma("unroll")                                                    \
            for (int i = 0; i < 4; i++)                                          \
                ra[i] = (rg < M) ? *(const float4*)(pa + 4 * i)                  \
                                 : make_float4(0.f, 0.f, 0.f, 0.f);              \
        }                                                                        \
    } while (0)

    // ---- A regs -> smem (relu(XA+XB+b) for gather, tf32 round) ----
#define STS_A(c, buf)                                                            \
    do {                                                                         \
        float* dsta = sA + (buf) * ASLOT + arow * 36 + akh;                      \
        int kg = (c) * 32 + akh;                                                 \
        _Pragma("unroll")                                                        \
        for (int i = 0; i < 4; i++) {                                            \
            float4 v = ra[i];                                                    \
            if (GATHER) {                                                        \
                float4 vb = rb4[i];                                              \
                float4 vc = *(const float4*)(bpre + kg + 4 * i);                 \
                v.x = fmaxf(v.x + vb.x + vc.x, 0.f);                             \
                v.y = fmaxf(v.y + vb.y + vc.y, 0.f);                             \
                v.z = fmaxf(v.z + vb.z + vc.z, 0.f);                             \
                v.w = fmaxf(v.w + vb.w + vc.w, 0.f);                             \
            }                                                                    \
            float4 o;                                                            \
            o.x = __uint_as_float(f2tf32(v.x));                                  \
            o.y = __uint_as_float(f2tf32(v.y));                                  \
            o.z = __uint_as_float(f2tf32(v.z));                                  \
            o.w = __uint_as_float(f2tf32(v.w));                                  \
            *(float4*)(dsta + 4 * i) = o;                                        \
        }                                                                        \
    } while (0)

    float acc[2][8][4];
#pragma unroll
    for (int mt = 0; mt < 2; mt++)
#pragma unroll
        for (int nt = 0; nt < 8; nt++)
#pragma unroll
            for (int j = 0; j < 4; j++) acc[mt][nt][j] = 0.f;

    // prologue
    ISSUE_B(0, 0);
    LOAD_A(0);
    STS_A(0, 0);

#pragma unroll
    for (int c = 0; c < NCH; c++) {
        const int buf = c & 1;
        asm volatile("cp.async.wait_group 0;" ::: "memory");
        __syncthreads();
        if (c + 1 < NCH) {
            ISSUE_B(c + 1, buf ^ 1);
            LOAD_A(c + 1);
        }
        // mma over chunk c
        const float* Ab = sA + buf * ASLOT + (wm * 32 + lr) * 36 + lc;
        const float* Bb = sB + buf * ASLOT + (wn * 64 + lr) * 36 + lc;
#pragma unroll
        for (int ks = 0; ks < 4; ks++) {
            uint32_t a[2][4];
#pragma unroll
            for (int mt = 0; mt < 2; mt++) {
                const float* ap = Ab + mt * 16 * 36 + ks * 8;
                a[mt][0] = __float_as_uint(ap[0]);
                a[mt][1] = __float_as_uint(ap[8 * 36]);
                a[mt][2] = __float_as_uint(ap[4]);
                a[mt][3] = __float_as_uint(ap[8 * 36 + 4]);
            }
#pragma unroll
            for (int nt = 0; nt < 8; nt++) {
                const float* bp = Bb + nt * 8 * 36 + ks * 8;
                uint32_t b0 = __float_as_uint(bp[0]);
                uint32_t b1 = __float_as_uint(bp[4]);
                mma8(acc[0][nt], a[0], b0, b1);
                mma8(acc[1][nt], a[1], b0, b1);
            }
        }
        if (c + 1 < NCH) STS_A(c + 1, buf ^ 1);
    }

    // ---- epilogue ----
#pragma unroll
    for (int mt = 0; mt < 2; mt++) {
#pragma unroll
        for (int part = 0; part < 2; part++) {
            const int rloc = wm * 32 + mt * 16 + lr + part * 8;
            const int rg = row0 + rloc;
            if (!(GATHER || SCATTER) && rg >= M) continue;
            float* outp = SCATTER ? (C + (size_t)sdst[rloc] * 256)
                                  : (C + (size_t)rg * 256);
#pragma unroll
            for (int nt = 0; nt < 8; nt++) {
                const int col = col0 + wn * 64 + nt * 8 + 2 * lc;
                float v0 = acc[mt][nt][part * 2 + 0];
                float v1 = acc[mt][nt][part * 2 + 1];
                if (ADD_BIAS) { v0 += bias[col]; v1 += bias[col + 1]; }
                if (RELU_OUT) { v0 = fmaxf(v0, 0.f); v1 = fmaxf(v1, 0.f); }
                if (SCATTER) {
                    atomicAdd(outp + col, v0);
                    atomicAdd(outp + col + 1, v1);
                } else {
                    *(float2*)(outp + col) = make_float2(v0, v1);
                }
            }
        }
    }
}

static constexpr size_t MM_SMEM = 4u * ASLOT * 4u + 256u * 4u;  // 74752 B

// ---------------- relu + layernorm with deg*b3 pre-add ----------------
__global__ void relu_ln_kernel(const float* __restrict__ IN,
                               const float* __restrict__ degf, const float* __restrict__ b3,
                               const float* __restrict__ g, const float* __restrict__ b,
                               float* __restrict__ OUT)
{
    int gid = blockIdx.x * blockDim.x + threadIdx.x;
    int node = gid >> 5;
    int lane = gid & 31;
    if (node >= N_NODES) return;
    const float* x = &IN[(size_t)node * 256];
    float dg = degf[node];
    float v[8];
    float s = 0.f;
#pragma unroll
    for (int q = 0; q < 2; q++) {
        float4 t = *(const float4*)(&x[lane * 8 + q * 4]);
        float4 bb = *(const float4*)(&b3[lane * 8 + q * 4]);
        v[q * 4 + 0] = fmaxf(fmaf(dg, bb.x, t.x), 0.f);
        v[q * 4 + 1] = fmaxf(fmaf(dg, bb.y, t.y), 0.f);
        v[q * 4 + 2] = fmaxf(fmaf(dg, bb.z, t.z), 0.f);
        v[q * 4 + 3] = fmaxf(fmaf(dg, bb.w, t.w), 0.f);
    }
#pragma unroll
    for (int i = 0; i < 8; i++) s += v[i];
#pragma unroll
    for (int o = 16; o > 0; o >>= 1) s += __shfl_xor_sync(0xffffffffu, s, o);
    float mu = s * (1.f / 256.f);
    float vs = 0.f;
#pragma unroll
    for (int i = 0; i < 8; i++) { float d = v[i] - mu; vs += d * d; }
#pragma unroll
    for (int o = 16; o > 0; o >>= 1) vs += __shfl_xor_sync(0xffffffffu, vs, o);
    float inv = rsqrtf(vs * (1.f / 256.f) + 1e-5f);
#pragma unroll
    for (int i = 0; i < 8; i++) {
        int c = lane * 8 + i;
        OUT[(size_t)node * 256 + c] = (v[i] - mu) * inv * g[c] + b[c];
    }
}

// ---------------- logits = T1 @ aw2 + ab2 (N x 32) ----------------
__global__ void logits_kernel(const float* __restrict__ T1, const float* __restrict__ aw2,
                              const float* __restrict__ ab2, float* __restrict__ LG)
{
    int c = threadIdx.x;
    int n = blockIdx.x * blockDim.y + threadIdx.y;
    if (n >= N_NODES) return;
    const float* t = &T1[(size_t)n * 256];
    float acc = ab2[c];
#pragma unroll 8
    for (int k = 0; k < 256; k++) acc = fmaf(t[k], aw2[k * 32 + c], acc);
    LG[n * 32 + c] = acc;
}

// ---------------- gumbel softmax + loss partials ----------------
__global__ void gumbel_kernel(const float* __restrict__ LG, const float* __restrict__ U,
                              float* __restrict__ sOut, float* __restrict__ colsum,
                              float* __restrict__ entsum)
{
    int lane = threadIdx.x & 31;
    int gw = (blockIdx.x * blockDim.x + threadIdx.x) >> 5;
    int nw = (gridDim.x * blockDim.x) >> 5;
    float colAcc = 0.f, entAcc = 0.f;
    for (int n = gw; n < N_NODES; n += nw) {
        float u = U[n * 32 + lane];
        float gn = -logf(-logf(u + EPSF) + EPSF);
        float v = LG[n * 32 + lane] + gn;
        float mx = v;
#pragma unroll
        for (int o = 16; o > 0; o >>= 1) mx = fmaxf(mx, __shfl_xor_sync(0xffffffffu, mx, o));
        float e = expf(v - mx);
        float ssum = e;
#pragma unroll
        for (int o = 16; o > 0; o >>= 1) ssum += __shfl_xor_sync(0xffffffffu, ssum, o);
        float sv = e / ssum;
        sOut[n * 32 + lane] = sv;
        colAcc += sv;
        entAcc += sv * logf(sv + EPSF);
    }
    atomicAdd(&colsum[lane], colAcc);
#pragma unroll
    for (int o = 16; o > 0; o >>= 1) entAcc += __shfl_xor_sync(0xffffffffu, entAcc, o);
    if (lane == 0) atomicAdd(entsum, entAcc);
}

__global__ void loss_kernel(const float* __restrict__ colsum, const float* __restrict__ entsum,
                            float* __restrict__ outLoss)
{
    int lane = threadIdx.x;
    float avg = colsum[lane] * (1.f / (float)N_NODES);
    float dv = avg * logf(avg + EPSF);
#pragma unroll
    for (int o = 16; o > 0; o >>= 1) dv += __shfl_xor_sync(0xffffffffu, dv, o);
    if (lane == 0) outLoss[0] = dv - entsum[0] * (1.f / (float)N_NODES);
}

__global__ void bounds_kernel(const int* __restrict__ batch, int* __restrict__ bstart)
{
    int t = threadIdx.x;
    if (t > B_BATCH) return;
    int lo = 0, hi = N_NODES;
    while (lo < hi) {
        int mid = (lo + hi) >> 1;
        if (batch[mid] < t) lo = mid + 1; else hi = mid;
    }
    bstart[t] = lo;
}

__global__ void pooled_kernel(const float* __restrict__ X2, const float* __restrict__ S,
                              const int* __restrict__ bstart, float* __restrict__ pooled)
{
    int b = blockIdx.x;
    int nchunk = gridDim.y;
    int s0 = bstart[b], s1 = bstart[b + 1];
    int len = s1 - s0;
    int per = (len + nchunk - 1) / nchunk;
    int n0 = s0 + blockIdx.y * per;
    int n1 = min(n0 + per, s1);
    if (n0 >= n1) return;

    int h = threadIdx.x;
    float acc[32];
#pragma unroll
    for (int k = 0; k < 32; k++) acc[k] = 0.f;

    __shared__ float st[8][33];
    for (int basei = n0; basei < n1; basei += 8) {
        __syncthreads();
        {
            int rr = threadIdx.x >> 5, cc = threadIdx.x & 31;
            st[rr][cc] = (basei + rr < n1) ? S[(size_t)(basei + rr) * 32 + cc] : 0.f;
        }
        __syncthreads();
        int cnt = min(8, n1 - basei);
        for (int rr = 0; rr < cnt; rr++) {
            float xv = X2[(size_t)(basei + rr) * 256 + h];
#pragma unroll
            for (int k = 0; k < 32; k++) acc[k] = fmaf(st[rr][k], xv, acc[k]);
        }
    }
#pragma unroll
    for (int k = 0; k < 32; k++)
        atomicAdd(&pooled[((size_t)b * 32 + k) * 256 + h], acc[k]);
}

__global__ void out2_kernel(const float* __restrict__ TO, const float* __restrict__ ow2,
                            const float* __restrict__ ob2, float* __restrict__ out)
{
    int r = blockIdx.x;
    int c = threadIdx.x;
    const float* t = &TO[(size_t)r * 256];
    float acc = ob2[c];
#pragma unroll 8
    for (int k = 0; k < 256; k++) acc = fmaf(t[k], ow2[k * 128 + c], acc);
    out[(size_t)r * 128 + c] = acc;
}

// ===================== launch =====================
extern "C" void kernel_launch(void* const* d_in, const int* in_sizes, int n_in,
                              void* d_out, int out_size)
{
    const float* x    = (const float*)d_in[0];
    const float* u    = (const float*)d_in[1];
    const int*   ei   = (const int*)d_in[2];
    const int*   batch= (const int*)d_in[3];
    const float* g1w1 = (const float*)d_in[4];
    const float* g1b1 = (const float*)d_in[5];
    const float* g1w2 = (const float*)d_in[6];
    const float* g1b2 = (const float*)d_in[7];
    const float* g1w3 = (const float*)d_in[8];
    const float* g1b3 = (const float*)d_in[9];
    const float* ln1g = (const float*)d_in[10];
    const float* ln1b = (const float*)d_in[11];
    const float* g2w1 = (const float*)d_in[12];
    const float* g2b1 = (const float*)d_in[13];
    const float* g2w2 = (const float*)d_in[14];
    const float* g2b2 = (const float*)d_in[15];
    const float* g2w3 = (const float*)d_in[16];
    const float* g2b3 = (const float*)d_in[17];
    const float* ln2g = (const float*)d_in[18];
    const float* ln2b = (const float*)d_in[19];
    const float* aw1  = (const float*)d_in[20];
    const float* ab1  = (const float*)d_in[21];
    const float* aw2  = (const float*)d_in[22];
    const float* ab2  = (const float*)d_in[23];
    const float* ow1  = (const float*)d_in[24];
    const float* ob1  = (const float*)d_in[25];
    const float* ow2  = (const float*)d_in[26];
    const float* ob2  = (const float*)d_in[27];

    const int* srcI = ei;
    const int* dstI = ei + N_EDGES;

    float* out        = (float*)d_out;
    float* out_latent = out;
    float* out_s      = out + B_BATCH * S_DIM * L_DIM;
    float* out_loss   = out_s + (size_t)N_NODES * S_DIM;

    float *pXA, *pXB, *pHS, *pACC, *pXLN, *pX2, *pT1, *pLG, *pDeg, *pPooled, *pTO, *pColsum, *pEntsum;
    float *pWT1a, *pWT1b, *pWT2, *pWT3, *pWT4a, *pWT4b, *pWT5, *pWT6, *pWTA, *pWTO;
    int* pBstart;
    cudaGetSymbolAddress((void**)&pXA, d_XA);
    cudaGetSymbolAddress((void**)&pXB, d_XB);
    cudaGetSymbolAddress((void**)&pHS, d_HS);
    cudaGetSymbolAddress((void**)&pACC, d_ACC);
    cudaGetSymbolAddress((void**)&pXLN, d_XLN);
    cudaGetSymbolAddress((void**)&pX2, d_X2);
    cudaGetSymbolAddress((void**)&pT1, d_T1);
    cudaGetSymbolAddress((void**)&pLG, d_LG);
    cudaGetSymbolAddress((void**)&pDeg, d_degf);
    cudaGetSymbolAddress((void**)&pPooled, d_pooled);
    cudaGetSymbolAddress((void**)&pTO, d_TO);
    cudaGetSymbolAddress((void**)&pColsum, d_colsum);
    cudaGetSymbolAddress((void**)&pEntsum, d_entsum);
    cudaGetSymbolAddress((void**)&pBstart, d_bstart);
    cudaGetSymbolAddress((void**)&pWT1a, d_WT1a);
    cudaGetSymbolAddress((void**)&pWT1b, d_WT1b);
    cudaGetSymbolAddress((void**)&pWT2, d_WT2);
    cudaGetSymbolAddress((void**)&pWT3, d_WT3);
    cudaGetSymbolAddress((void**)&pWT4a, d_WT4a);
    cudaGetSymbolAddress((void**)&pWT4b, d_WT4b);
    cudaGetSymbolAddress((void**)&pWT5, d_WT5);
    cudaGetSymbolAddress((void**)&pWT6, d_WT6);
    cudaGetSymbolAddress((void**)&pWTA, d_WTA);
    cudaGetSymbolAddress((void**)&pWTO, d_WTO);

    cudaFuncSetAttribute(mma_gemm<0,0,0,0,64>,  cudaFuncAttributeMaxDynamicSharedMemorySize, (int)MM_SMEM);
    cudaFuncSetAttribute(mma_gemm<1,1,1,1,256>, cudaFuncAttributeMaxDynamicSharedMemorySize, (int)MM_SMEM);
    cudaFuncSetAttribute(mma_gemm<0,0,0,0,256>, cudaFuncAttributeMaxDynamicSharedMemorySize, (int)MM_SMEM);
    cudaFuncSetAttribute(mma_gemm<0,0,1,1,256>, cudaFuncAttributeMaxDynamicSharedMemorySize, (int)MM_SMEM);

    const dim3 GN((N_NODES + 127) / 128, 2);   // 157 x 2
    const dim3 GE(N_EDGES / 128, 2);           // 2500 x 2
    dim3 tb32(32, 8);

    // ---- layer 1 ----
    zero_kernel<<<256, 256>>>(pHS, N_NODES * H_DIM);
    transpose_kernel<<<dim3(8, 2), tb32>>>(g1w1,            pWT1a, 64, 256);
    transpose_kernel<<<dim3(8, 2), tb32>>>(g1w1 + 64 * 256, pWT1b, 64, 256);
    transpose_kernel<<<dim3(8, 8), tb32>>>(g1w2, pWT2, 256, 256);
    mma_gemm<0,0,0,0,64><<<GN, 256, MM_SMEM>>>(x, N_NODES, nullptr, nullptr, nullptr,
                                               nullptr, nullptr, pWT1a, nullptr, pXA);
    mma_gemm<0,0,0,0,64><<<GN, 256, MM_SMEM>>>(x, N_NODES, nullptr, nullptr, nullptr,
                                               nullptr, nullptr, pWT1b, nullptr, pXB);
    mma_gemm<1,1,1,1,256><<<GE, 256, MM_SMEM>>>(nullptr, N_EDGES, pXA, pXB, g1b1,
                                                srcI, dstI, pWT2, g1b2, pHS);
    transpose_kernel<<<dim3(8, 8), tb32>>>(g1w3, pWT3, 256, 256);
    mma_gemm<0,0,0,0,256><<<GN, 256, MM_SMEM>>>(pHS, N_NODES, nullptr, nullptr, nullptr,
                                                nullptr, nullptr, pWT3, nullptr, pACC);
    zero_kernel<<<128, 256>>>(pDeg, N_NODES);
    deg_kernel<<<256, 256>>>(dstI, pDeg);
    relu_ln_kernel<<<(N_NODES * 32 + 255) / 256, 256>>>(pACC, pDeg, g1b3, ln1g, ln1b, pXLN);

    // ---- layer 2 ----
    zero_kernel<<<256, 256>>>(pHS, N_NODES * H_DIM);
    transpose_kernel<<<dim3(8, 8), tb32>>>(g2w1,             pWT4a, 256, 256);
    transpose_kernel<<<dim3(8, 8), tb32>>>(g2w1 + 256 * 256, pWT4b, 256, 256);
    transpose_kernel<<<dim3(8, 8), tb32>>>(g2w2, pWT5, 256, 256);
    mma_gemm<0,0,0,0,256><<<GN, 256, MM_SMEM>>>(pXLN, N_NODES, nullptr, nullptr, nullptr,
                                                nullptr, nullptr, pWT4a, nullptr, pXA);
    mma_gemm<0,0,0,0,256><<<GN, 256, MM_SMEM>>>(pXLN, N_NODES, nullptr, nullptr, nullptr,
                                                nullptr, nullptr, pWT4b, nullptr, pXB);
    mma_gemm<1,1,1,1,256><<<GE, 256, MM_SMEM>>>(nullptr, N_EDGES, pXA, pXB, g2b1,
                                                srcI, dstI, pWT5, g2b2, pHS);
    transpose_kernel<<<dim3(8, 8), tb32>>>(g2w3, pWT6, 256, 256);
    mma_gemm<0,0,0,0,256><<<GN, 256, MM_SMEM>>>(pHS, N_NODES, nullptr, nullptr, nullptr,
                                                nullptr, nullptr, pWT6, nullptr, pACC);
    relu_ln_kernel<<<(N_NODES * 32 + 255) / 256, 256>>>(pACC, pDeg, g2b3, ln2g, ln2b, pX2);

    // ---- assignment ----
    transpose_kernel<<<dim3(8, 8), tb32>>>(aw1, pWTA, 256, 256);
    mma_gemm<0,0,1,1,256><<<GN, 256, MM_SMEM>>>(pX2, N_NODES, nullptr, nullptr, nullptr,
                                                nullptr, nullptr, pWTA, ab1, pT1);
    {
        dim3 lb(32, 8);
        logits_kernel<<<(N_NODES + 7) / 8, lb>>>(pT1, aw2, ab2, pLG);
    }
    zero_kernel<<<1, 32>>>(pColsum, S_DIM);
    zero_kernel<<<1, 32>>>(pEntsum, 1);
    gumbel_kernel<<<80, 256>>>(pLG, u, out_s, pColsum, pEntsum);
    loss_kernel<<<1, 32>>>(pColsum, pEntsum, out_loss);

    // ---- pooling ----
    bounds_kernel<<<1, 32>>>(batch, pBstart);
    zero_kernel<<<32, 256>>>(pPooled, B_BATCH * S_DIM * H_DIM);
    {
        dim3 pg(B_BATCH, 8);
        pooled_kernel<<<pg, 256>>>(pX2, out_s, pBstart, pPooled);
    }

    // ---- output MLP ----
    transpose_kernel<<<dim3(8, 8), tb32>>>(ow1, pWTO, 256, 256);
    mma_gemm<0,0,1,1,256><<<dim3(4, 2), 256, MM_SMEM>>>(
        pPooled, B_BATCH * S_DIM, nullptr, nullptr, nullptr,
        nullptr, nullptr, pWTO, ob1, pTO);
    out2_kernel<<<B_BATCH * S_DIM, 128>>>(pTO, ow2, ob2, out_latent);
}

// round 5
// speedup vs baseline: 2.9103x; 1.0446x over previous
#include <cuda_runtime.h>
#include <cstdint>

// Problem constants
#define N_NODES 20000
#define N_EDGES 320000
#define F_IN    64
#define H_DIM   256
#define S_DIM   32
#define L_DIM   128
#define B_BATCH 16
#define EPSF    1e-9f

// ===================== helpers =====================
__device__ __forceinline__ uint32_t smem_u32(const void* p) {
    uint32_t a;
    asm("{ .reg .u64 t; cvta.to.shared.u64 t, %1; cvt.u32.u64 %0, t; }" : "=r"(a) : "l"(p));
    return a;
}
__device__ __forceinline__ uint32_t f2tf32(float f) {
    uint32_t r;
    asm("cvt.rna.tf32.f32 %0, %1;" : "=r"(r) : "f"(f));
    return r;
}
__device__ __forceinline__ void mma8(float* c, const uint32_t* a, uint32_t b0, uint32_t b1) {
    asm volatile(
        "mma.sync.aligned.m16n8k8.row.col.f32.tf32.tf32.f32 "
        "{%0,%1,%2,%3}, {%4,%5,%6,%7}, {%8,%9}, {%0,%1,%2,%3};"
        : "+f"(c[0]), "+f"(c[1]), "+f"(c[2]), "+f"(c[3])
        : "r"(a[0]), "r"(a[1]), "r"(a[2]), "r"(a[3]), "r"(b0), "r"(b1));
}
__device__ __forceinline__ void red2(float* addr, float v0, float v1) {
    asm volatile("red.global.add.v2.f32 [%0], {%1, %2};"
                 :: "l"(addr), "f"(v0), "f"(v1) : "memory");
}

// ===================== device scratch =====================
__device__ float d_XA[N_NODES * H_DIM];
__device__ float d_XB[N_NODES * H_DIM];
__device__ float d_HS1[N_NODES * H_DIM];
__device__ float d_HS2[N_NODES * H_DIM];
__device__ float d_ACC[N_NODES * H_DIM];
__device__ float d_XLN[N_NODES * H_DIM];
__device__ float d_X2[N_NODES * H_DIM];
__device__ float d_T1[N_NODES * H_DIM];
__device__ float d_LG[N_NODES * S_DIM];
__device__ float d_degf[N_NODES];
__device__ float d_pooled[B_BATCH * S_DIM * H_DIM];
__device__ float d_TO[B_BATCH * S_DIM * H_DIM];
__device__ float d_colsum[S_DIM];
__device__ float d_entsum[1];
__device__ int   d_bstart[B_BATCH + 1];
// transposed (and tf32-rounded) weights [N][K]
__device__ float d_WT1a[256 * 64];
__device__ float d_WT1b[256 * 64];
__device__ float d_WT2[256 * 256];
__device__ float d_WT3[256 * 256];
__device__ float d_WT4a[256 * 256];
__device__ float d_WT4b[256 * 256];
__device__ float d_WT5[256 * 256];
__device__ float d_WT6[256 * 256];
__device__ float d_WTA[256 * 256];
__device__ float d_WTO[256 * 256];

// ===================== fused zero =====================
struct ZeroPars { float* p[6]; int n[6]; };
__global__ void zero_all(ZeroPars zp) {
    int r = blockIdx.y;
    float* p = zp.p[r];
    int n = zp.n[r];
    int i = blockIdx.x * blockDim.x + threadIdx.x;
    int st = gridDim.x * blockDim.x;
    for (; i < n; i += st) p[i] = 0.f;
}

__global__ void deg_kernel(const int* __restrict__ dst, float* __restrict__ degf) {
    int i = blockIdx.x * blockDim.x + threadIdx.x;
    int st = gridDim.x * blockDim.x;
    for (; i < N_EDGES; i += st) atomicAdd(&degf[dst[i]], 1.f);
}

// ===================== batched transpose (tf32 round) =====================
// For each matrix m: out[c][r] = tf32(in[r][c]); in is [R][256]
struct TransPars { const float* src[10]; float* dst[10]; int R[10]; };
__global__ void transpose_all(TransPars tp) {
    __shared__ float t[32][33];
    int m = blockIdx.z;
    const float* in = tp.src[m];
    float* out = tp.dst[m];
    int R = tp.R[m];
    int c0 = blockIdx.x * 32, r0 = blockIdx.y * 32;
    if (r0 >= R) return;
    for (int j = threadIdx.y; j < 32; j += 8) {
        int r = r0 + j, c = c0 + threadIdx.x;
        t[j][threadIdx.x] = (r < R) ? in[(size_t)r * 256 + c] : 0.f;
    }
    __syncthreads();
    for (int j = threadIdx.y; j < 32; j += 8) {
        int oc = c0 + j, orr = r0 + threadIdx.x;
        if (orr < R)
            out[(size_t)oc * R + orr] = __uint_as_float(f2tf32(t[threadIdx.x][j]));
    }
}

// ===================== tf32 mma.sync GEMM =====================
// CTA tile 128(M) x 128(N), grid.y picks the 128-col block. K chunks of 32.
// 8 warps: wm = wid&3 (4 x 32 rows), wn = wid>>2 (2 x 64 cols). Warp tile 32x64.
// GATHER: A row = relu(XA[gdst] + XB[gsrc] + bpre), K=256.
// SCATTER: epilogue red.v2 into C[gdst] (bias/relu applied per edge first).
// Smem stride 36 floats (36 mod 32 == 4) -> conflict-free mma fragment loads.
#define ASLOT 4608  // 128*36 floats

template<int GATHER, int SCATTER, int RELU_OUT, int ADD_BIAS, int KLEN>
__global__ void __launch_bounds__(256, 2) mma_gemm(
    const float* __restrict__ A, int M,
    const float* __restrict__ XA, const float* __restrict__ XB,
    const float* __restrict__ bpre,
    const int* __restrict__ gsrc, const int* __restrict__ gdst,
    const float* __restrict__ WT,   // [256][KLEN] K-major, tf32-rounded
    const float* __restrict__ bias,
    float* __restrict__ C)
{
    extern __shared__ float sm[];
    float* sA = sm;                    // 2 * ASLOT
    float* sB = sm + 2 * ASLOT;        // 2 * ASLOT
    int* sdst = (int*)(sm + 4 * ASLOT);
    int* ssrc = sdst + 128;

    const int tid  = threadIdx.x;
    const int lane = tid & 31;
    const int wid  = tid >> 5;
    const int wm = wid & 3;
    const int wn = wid >> 2;
    const int lr = lane >> 2;
    const int lc = lane & 3;
    const int row0 = blockIdx.x * 128;
    const int col0 = blockIdx.y * 128;
    constexpr int NCH = KLEN / 32;

    if ((GATHER || SCATTER) && tid < 128) {
        sdst[tid] = gdst[row0 + tid];
        if (GATHER) ssrc[tid] = gsrc[row0 + tid];
    }
    if (GATHER || SCATTER) __syncthreads();

    const int arow = tid >> 1;
    const int akh  = (tid & 1) << 4;
    const int bn   = tid >> 1;
    const int bkh  = (tid & 1) << 4;
    const uint32_t sB_addr = smem_u32(sB);
    const float* WTb = WT + (size_t)(col0 + bn) * KLEN + bkh;

    float4 ra[4], rb4[4];

    // ---- B issue (cp.async, 4x16B per thread) ----
#define ISSUE_B(c, buf)                                                          \
    do {                                                                         \
        uint32_t dstb = sB_addr + (uint32_t)((buf) * ASLOT + bn * 36 + bkh) * 4u;\
        const float* srcb = WTb + (c) * 32;                                      \
        _Pragma("unroll")                                                        \
        for (int i = 0; i < 4; i++)                                              \
            asm volatile("cp.async.ca.shared.global [%0], [%1], 16;" ::          \
                         "r"(dstb + (uint32_t)i * 16u), "l"(srcb + i * 4) : "memory"); \
        asm volatile("cp.async.commit_group;" ::: "memory");                     \
    } while (0)

    // ---- A load to regs ----
#define LOAD_A(c)                                                                \
    do {                                                                         \
        int kg = (c) * 32 + akh;                                                 \
        if (GATHER) {                                                            \
            const float* pa = XA + (size_t)sdst[arow] * 256 + kg;                \
            const float* pb = XB + (size_t)ssrc[arow] * 256 + kg;                \
            _Pragma("unroll")                                                    \
            for (int i = 0; i < 4; i++) {                                        \
                ra[i]  = *(const float4*)(pa + 4 * i);                           \
                rb4[i] = *(const float4*)(pb + 4 * i);                           \
            }                                                                    \
        } else {                                                                 \
            int rg = row0 + arow;                                                \
            const float* pa = A + (size_t)rg * KLEN + kg;                        \
            _Pragma("unroll")                                                    \
            for (int i = 0; i < 4; i++)                                          \
                ra[i] = (rg < M) ? *(const float4*)(pa + 4 * i)                  \
                                 : make_float4(0.f, 0.f, 0.f, 0.f);              \
        }                                                                        \
    } while (0)

    // ---- A regs -> smem (relu(XA+XB+b) for gather, tf32 round) ----
#define STS_A(c, buf)                                                            \
    do {                                                                         \
        float* dsta = sA + (buf) * ASLOT + arow * 36 + akh;                      \
        int kg = (c) * 32 + akh;                                                 \
        _Pragma("unroll")                                                        \
        for (int i = 0; i < 4; i++) {                                            \
            float4 v = ra[i];                                                    \
            if (GATHER) {                                                        \
                float4 vb = rb4[i];                                              \
                float4 vc = *(const float4*)(bpre + kg + 4 * i);                 \
                v.x = fmaxf(v.x + vb.x + vc.x, 0.f);                             \
                v.y = fmaxf(v.y + vb.y + vc.y, 0.f);                             \
                v.z = fmaxf(v.z + vb.z + vc.z, 0.f);                             \
                v.w = fmaxf(v.w + vb.w + vc.w, 0.f);                             \
            }                                                                    \
            float4 o;                                                            \
            o.x = __uint_as_float(f2tf32(v.x));                                  \
            o.y = __uint_as_float(f2tf32(v.y));                                  \
            o.z = __uint_as_float(f2tf32(v.z));                                  \
            o.w = __uint_as_float(f2tf32(v.w));                                  \
            *(float4*)(dsta + 4 * i) = o;                                        \
        }                                                                        \
    } while (0)

    float acc[2][8][4];
#pragma unroll
    for (int mt = 0; mt < 2; mt++)
#pragma unroll
        for (int nt = 0; nt < 8; nt++)
#pragma unroll
            for (int j = 0; j < 4; j++) acc[mt][nt][j] = 0.f;

    // prologue
    ISSUE_B(0, 0);
    LOAD_A(0);
    STS_A(0, 0);

#pragma unroll
    for (int c = 0; c < NCH; c++) {
        const int buf = c & 1;
        asm volatile("cp.async.wait_group 0;" ::: "memory");
        __syncthreads();
        if (c + 1 < NCH) {
            ISSUE_B(c + 1, buf ^ 1);
            LOAD_A(c + 1);
        }
        // mma over chunk c
        const float* Ab = sA + buf * ASLOT + (wm * 32 + lr) * 36 + lc;
        const float* Bb = sB + buf * ASLOT + (wn * 64 + lr) * 36 + lc;
#pragma unroll
        for (int ks = 0; ks < 4; ks++) {
            uint32_t a[2][4];
#pragma unroll
            for (int mt = 0; mt < 2; mt++) {
                const float* ap = Ab + mt * 16 * 36 + ks * 8;
                a[mt][0] = __float_as_uint(ap[0]);
                a[mt][1] = __float_as_uint(ap[8 * 36]);
                a[mt][2] = __float_as_uint(ap[4]);
                a[mt][3] = __float_as_uint(ap[8 * 36 + 4]);
            }
#pragma unroll
            for (int nt = 0; nt < 8; nt++) {
                const float* bp = Bb + nt * 8 * 36 + ks * 8;
                uint32_t b0 = __float_as_uint(bp[0]);
                uint32_t b1 = __float_as_uint(bp[4]);
                mma8(acc[0][nt], a[0], b0, b1);
                mma8(acc[1][nt], a[1], b0, b1);
            }
        }
        if (c + 1 < NCH) STS_A(c + 1, buf ^ 1);
    }

    // ---- epilogue ----
#pragma unroll
    for (int mt = 0; mt < 2; mt++) {
#pragma unroll
        for (int part = 0; part < 2; part++) {
            const int rloc = wm * 32 + mt * 16 + lr + part * 8;
            const int rg = row0 + rloc;
            if (!(GATHER || SCATTER) && rg >= M) continue;
            float* outp = SCATTER ? (C + (size_t)sdst[rloc] * 256)
                                  : (C + (size_t)rg * 256);
#pragma unroll
            for (int nt = 0; nt < 8; nt++) {
                const int col = col0 + wn * 64 + nt * 8 + 2 * lc;
                float v0 = acc[mt][nt][part * 2 + 0];
                float v1 = acc[mt][nt][part * 2 + 1];
                if (ADD_BIAS) { v0 += bias[col]; v1 += bias[col + 1]; }
                if (RELU_OUT) { v0 = fmaxf(v0, 0.f); v1 = fmaxf(v1, 0.f); }
                if (SCATTER) {
                    red2(outp + col, v0, v1);
                } else {
                    *(float2*)(outp + col) = make_float2(v0, v1);
                }
            }
        }
    }
}

static constexpr size_t MM_SMEM = 4u * ASLOT * 4u + 256u * 4u;  // 74752 B

// ---------------- relu + layernorm with deg*b3 pre-add ----------------
__global__ void relu_ln_kernel(const float* __restrict__ IN,
                               const float* __restrict__ degf, const float* __restrict__ b3,
                               const float* __restrict__ g, const float* __restrict__ b,
                               float* __restrict__ OUT)
{
    int gid = blockIdx.x * blockDim.x + threadIdx.x;
    int node = gid >> 5;
    int lane = gid & 31;
    if (node >= N_NODES) return;
    const float* x = &IN[(size_t)node * 256];
    float dg = degf[node];
    float v[8];
    float s = 0.f;
#pragma unroll
    for (int q = 0; q < 2; q++) {
        float4 t = *(const float4*)(&x[lane * 8 + q * 4]);
        float4 bb = *(const float4*)(&b3[lane * 8 + q * 4]);
        v[q * 4 + 0] = fmaxf(fmaf(dg, bb.x, t.x), 0.f);
        v[q * 4 + 1] = fmaxf(fmaf(dg, bb.y, t.y), 0.f);
        v[q * 4 + 2] = fmaxf(fmaf(dg, bb.z, t.z), 0.f);
        v[q * 4 + 3] = fmaxf(fmaf(dg, bb.w, t.w), 0.f);
    }
#pragma unroll
    for (int i = 0; i < 8; i++) s += v[i];
#pragma unroll
    for (int o = 16; o > 0; o >>= 1) s += __shfl_xor_sync(0xffffffffu, s, o);
    float mu = s * (1.f / 256.f);
    float vs = 0.f;
#pragma unroll
    for (int i = 0; i < 8; i++) { float d = v[i] - mu; vs += d * d; }
#pragma unroll
    for (int o = 16; o > 0; o >>= 1) vs += __shfl_xor_sync(0xffffffffu, vs, o);
    float inv = rsqrtf(vs * (1.f / 256.f) + 1e-5f);
#pragma unroll
    for (int i = 0; i < 8; i++) {
        int c = lane * 8 + i;
        OUT[(size_t)node * 256 + c] = (v[i] - mu) * inv * g[c] + b[c];
    }
}

// ---------------- logits = T1 @ aw2 + ab2 (N x 32) ----------------
__global__ void logits_kernel(const float* __restrict__ T1, const float* __restrict__ aw2,
                              const float* __restrict__ ab2, float* __restrict__ LG)
{
    int c = threadIdx.x;
    int n = blockIdx.x * blockDim.y + threadIdx.y;
    if (n >= N_NODES) return;
    const float* t = &T1[(size_t)n * 256];
    float acc = ab2[c];
#pragma unroll 8
    for (int k = 0; k < 256; k++) acc = fmaf(t[k], aw2[k * 32 + c], acc);
    LG[n * 32 + c] = acc;
}

// ---------------- gumbel softmax + loss partials ----------------
__global__ void gumbel_kernel(const float* __restrict__ LG, const float* __restrict__ U,
                              float* __restrict__ sOut, float* __restrict__ colsum,
                              float* __restrict__ entsum)
{
    int lane = threadIdx.x & 31;
    int gw = (blockIdx.x * blockDim.x + threadIdx.x) >> 5;
    int nw = (gridDim.x * blockDim.x) >> 5;
    float colAcc = 0.f, entAcc = 0.f;
    for (int n = gw; n < N_NODES; n += nw) {
        float u = U[n * 32 + lane];
        float gn = -logf(-logf(u + EPSF) + EPSF);
        float v = LG[n * 32 + lane] + gn;
        float mx = v;
#pragma unroll
        for (int o = 16; o > 0; o >>= 1) mx = fmaxf(mx, __shfl_xor_sync(0xffffffffu, mx, o));
        float e = expf(v - mx);
        float ssum = e;
#pragma unroll
        for (int o = 16; o > 0; o >>= 1) ssum += __shfl_xor_sync(0xffffffffu, ssum, o);
        float sv = e / ssum;
        sOut[n * 32 + lane] = sv;
        colAcc += sv;
        entAcc += sv * logf(sv + EPSF);
    }
    atomicAdd(&colsum[lane], colAcc);
#pragma unroll
    for (int o = 16; o > 0; o >>= 1) entAcc += __shfl_xor_sync(0xffffffffu, entAcc, o);
    if (lane == 0) atomicAdd(entsum, entAcc);
}

__global__ void loss_kernel(const float* __restrict__ colsum, const float* __restrict__ entsum,
                            float* __restrict__ outLoss)
{
    int lane = threadIdx.x;
    float avg = colsum[lane] * (1.f / (float)N_NODES);
    float dv = avg * logf(avg + EPSF);
#pragma unroll
    for (int o = 16; o > 0; o >>= 1) dv += __shfl_xor_sync(0xffffffffu, dv, o);
    if (lane == 0) outLoss[0] = dv - entsum[0] * (1.f / (float)N_NODES);
}

__global__ void bounds_kernel(const int* __restrict__ batch, int* __restrict__ bstart)
{
    int t = threadIdx.x;
    if (t > B_BATCH) return;
    int lo = 0, hi = N_NODES;
    while (lo < hi) {
        int mid = (lo + hi) >> 1;
        if (batch[mid] < t) lo = mid + 1; else hi = mid;
    }
    bstart[t] = lo;
}

__global__ void pooled_kernel(const float* __restrict__ X2, const float* __restrict__ S,
                              const int* __restrict__ bstart, float* __restrict__ pooled)
{
    int b = blockIdx.x;
    int nchunk = gridDim.y;
    int s0 = bstart[b], s1 = bstart[b + 1];
    int len = s1 - s0;
    int per = (len + nchunk - 1) / nchunk;
    int n0 = s0 + blockIdx.y * per;
    int n1 = min(n0 + per, s1);
    if (n0 >= n1) return;

    int h = threadIdx.x;
    float acc[32];
#pragma unroll
    for (int k = 0; k < 32; k++) acc[k] = 0.f;

    __shared__ float st[8][33];
    for (int basei = n0; basei < n1; basei += 8) {
        __syncthreads();
        {
            int rr = threadIdx.x >> 5, cc = threadIdx.x & 31;
            st[rr][cc] = (basei + rr < n1) ? S[(size_t)(basei + rr) * 32 + cc] : 0.f;
        }
        __syncthreads();
        int cnt = min(8, n1 - basei);
        for (int rr = 0; rr < cnt; rr++) {
            float xv = X2[(size_t)(basei + rr) * 256 + h];
#pragma unroll
            for (int k = 0; k < 32; k++) acc[k] = fmaf(st[rr][k], xv, acc[k]);
        }
    }
#pragma unroll
    for (int k = 0; k < 32; k++)
        atomicAdd(&pooled[((size_t)b * 32 + k) * 256 + h], acc[k]);
}

__global__ void out2_kernel(const float* __restrict__ TO, const float* __restrict__ ow2,
                            const float* __restrict__ ob2, float* __restrict__ out)
{
    int r = blockIdx.x;
    int c = threadIdx.x;
    const float* t = &TO[(size_t)r * 256];
    float acc = ob2[c];
#pragma unroll 8
    for (int k = 0; k < 256; k++) acc = fmaf(t[k], ow2[k * 128 + c], acc);
    out[(size_t)r * 128 + c] = acc;
}

// ===================== launch =====================
extern "C" void kernel_launch(void* const* d_in, const int* in_sizes, int n_in,
                              void* d_out, int out_size)
{
    const float* x    = (const float*)d_in[0];
    const float* u    = (const float*)d_in[1];
    const int*   ei   = (const int*)d_in[2];
    const int*   batch= (const int*)d_in[3];
    const float* g1w1 = (const float*)d_in[4];
    const float* g1b1 = (const float*)d_in[5];
    const float* g1w2 = (const float*)d_in[6];
    const float* g1b2 = (const float*)d_in[7];
    const float* g1w3 = (const float*)d_in[8];
    const float* g1b3 = (const float*)d_in[9];
    const float* ln1g = (const float*)d_in[10];
    const float* ln1b = (const float*)d_in[11];
    const float* g2w1 = (const float*)d_in[12];
    const float* g2b1 = (const float*)d_in[13];
    const float* g2w2 = (const float*)d_in[14];
    const float* g2b2 = (const float*)d_in[15];
    const float* g2w3 = (const float*)d_in[16];
    const float* g2b3 = (const float*)d_in[17];
    const float* ln2g = (const float*)d_in[18];
    const float* ln2b = (const float*)d_in[19];
    const float* aw1  = (const float*)d_in[20];
    const float* ab1  = (const float*)d_in[21];
    const float* aw2  = (const float*)d_in[22];
    const float* ab2  = (const float*)d_in[23];
    const float* ow1  = (const float*)d_in[24];
    const float* ob1  = (const float*)d_in[25];
    const float* ow2  = (const float*)d_in[26];
    const float* ob2  = (const float*)d_in[27];

    const int* srcI = ei;
    const int* dstI = ei + N_EDGES;

    float* out        = (float*)d_out;
    float* out_latent = out;
    float* out_s      = out + B_BATCH * S_DIM * L_DIM;
    float* out_loss   = out_s + (size_t)N_NODES * S_DIM;

    float *pXA, *pXB, *pHS1, *pHS2, *pACC, *pXLN, *pX2, *pT1, *pLG, *pDeg, *pPooled, *pTO, *pColsum, *pEntsum;
    float *pWT1a, *pWT1b, *pWT2, *pWT3, *pWT4a, *pWT4b, *pWT5, *pWT6, *pWTA, *pWTO;
    int* pBstart;
    cudaGetSymbolAddress((void**)&pXA, d_XA);
    cudaGetSymbolAddress((void**)&pXB, d_XB);
    cudaGetSymbolAddress((void**)&pHS1, d_HS1);
    cudaGetSymbolAddress((void**)&pHS2, d_HS2);
    cudaGetSymbolAddress((void**)&pACC, d_ACC);
    cudaGetSymbolAddress((void**)&pXLN, d_XLN);
    cudaGetSymbolAddress((void**)&pX2, d_X2);
    cudaGetSymbolAddress((void**)&pT1, d_T1);
    cudaGetSymbolAddress((void**)&pLG, d_LG);
    cudaGetSymbolAddress((void**)&pDeg, d_degf);
    cudaGetSymbolAddress((void**)&pPooled, d_pooled);
    cudaGetSymbolAddress((void**)&pTO, d_TO);
    cudaGetSymbolAddress((void**)&pColsum, d_colsum);
    cudaGetSymbolAddress((void**)&pEntsum, d_entsum);
    cudaGetSymbolAddress((void**)&pBstart, d_bstart);
    cudaGetSymbolAddress((void**)&pWT1a, d_WT1a);
    cudaGetSymbolAddress((void**)&pWT1b, d_WT1b);
    cudaGetSymbolAddress((void**)&pWT2, d_WT2);
    cudaGetSymbolAddress((void**)&pWT3, d_WT3);
    cudaGetSymbolAddress((void**)&pWT4a, d_WT4a);
    cudaGetSymbolAddress((void**)&pWT4b, d_WT4b);
    cudaGetSymbolAddress((void**)&pWT5, d_WT5);
    cudaGetSymbolAddress((void**)&pWT6, d_WT6);
    cudaGetSymbolAddress((void**)&pWTA, d_WTA);
    cudaGetSymbolAddress((void**)&pWTO, d_WTO);

    cudaFuncSetAttribute(mma_gemm<0,0,0,0,64>,  cudaFuncAttributeMaxDynamicSharedMemorySize, (int)MM_SMEM);
    cudaFuncSetAttribute(mma_gemm<1,1,1,1,256>, cudaFuncAttributeMaxDynamicSharedMemorySize, (int)MM_SMEM);
    cudaFuncSetAttribute(mma_gemm<0,0,0,0,256>, cudaFuncAttributeMaxDynamicSharedMemorySize, (int)MM_SMEM);
    cudaFuncSetAttribute(mma_gemm<0,0,1,1,256>, cudaFuncAttributeMaxDynamicSharedMemorySize, (int)MM_SMEM);

    const dim3 GN((N_NODES + 127) / 128, 2);   // 157 x 2
    const dim3 GE(N_EDGES / 128, 2);           // 2500 x 2

    // ---- fused zeroing + degree + all weight transposes ----
    {
        ZeroPars zp;
        zp.p[0] = pHS1;    zp.n[0] = N_NODES * H_DIM;
        zp.p[1] = pHS2;    zp.n[1] = N_NODES * H_DIM;
        zp.p[2] = pDeg;    zp.n[2] = N_NODES;
        zp.p[3] = pColsum; zp.n[3] = S_DIM;
        zp.p[4] = pEntsum; zp.n[4] = 1;
        zp.p[5] = pPooled; zp.n[5] = B_BATCH * S_DIM * H_DIM;
        zero_all<<<dim3(160, 6), 256>>>(zp);
    }
    deg_kernel<<<256, 256>>>(dstI, pDeg);
    {
        TransPars tp;
        tp.src[0] = g1w1;             tp.dst[0] = pWT1a; tp.R[0] = 64;
        tp.src[1] = g1w1 + 64 * 256;  tp.dst[1] = pWT1b; tp.R[1] = 64;
        tp.src[2] = g1w2;             tp.dst[2] = pWT2;  tp.R[2] = 256;
        tp.src[3] = g1w3;             tp.dst[3] = pWT3;  tp.R[3] = 256;
        tp.src[4] = g2w1;             tp.dst[4] = pWT4a; tp.R[4] = 256;
        tp.src[5] = g2w1 + 256 * 256; tp.dst[5] = pWT4b; tp.R[5] = 256;
        tp.src[6] = g2w2;             tp.dst[6] = pWT5;  tp.R[6] = 256;
        tp.src[7] = g2w3;             tp.dst[7] = pWT6;  tp.R[7] = 256;
        tp.src[8] = aw1;              tp.dst[8] = pWTA;  tp.R[8] = 256;
        tp.src[9] = ow1;              tp.dst[9] = pWTO;  tp.R[9] = 256;
        dim3 tg(8, 8, 10), tb(32, 8);
        transpose_all<<<tg, tb>>>(tp);
    }

    // ---- layer 1 ----
    mma_gemm<0,0,0,0,64><<<GN, 256, MM_SMEM>>>(x, N_NODES, nullptr, nullptr, nullptr,
                                               nullptr, nullptr, pWT1a, nullptr, pXA);
    mma_gemm<0,0,0,0,64><<<GN, 256, MM_SMEM>>>(x, N_NODES, nullptr, nullptr, nullptr,
                                               nullptr, nullptr, pWT1b, nullptr, pXB);
    mma_gemm<1,1,1,1,256><<<GE, 256, MM_SMEM>>>(nullptr, N_EDGES, pXA, pXB, g1b1,
                                                srcI, dstI, pWT2, g1b2, pHS1);
    mma_gemm<0,0,0,0,256><<<GN, 256, MM_SMEM>>>(pHS1, N_NODES, nullptr, nullptr, nullptr,
                                                nullptr, nullptr, pWT3, nullptr, pACC);
    relu_ln_kernel<<<(N_NODES * 32 + 255) / 256, 256>>>(pACC, pDeg, g1b3, ln1g, ln1b, pXLN);

    // ---- layer 2 ----
    mma_gemm<0,0,0,0,256><<<GN, 256, MM_SMEM>>>(pXLN, N_NODES, nullptr, nullptr, nullptr,
                                                nullptr, nullptr, pWT4a, nullptr, pXA);
    mma_gemm<0,0,0,0,256><<<GN, 256, MM_SMEM>>>(pXLN, N_NODES, nullptr, nullptr, nullptr,
                                                nullptr, nullptr, pWT4b, nullptr, pXB);
    mma_gemm<1,1,1,1,256><<<GE, 256, MM_SMEM>>>(nullptr, N_EDGES, pXA, pXB, g2b1,
                                                srcI, dstI, pWT5, g2b2, pHS2);
    mma_gemm<0,0,0,0,256><<<GN, 256, MM_SMEM>>>(pHS2, N_NODES, nullptr, nullptr, nullptr,
                                                nullptr, nullptr, pWT6, nullptr, pACC);
    relu_ln_kernel<<<(N_NODES * 32 + 255) / 256, 256>>>(pACC, pDeg, g2b3, ln2g, ln2b, pX2);

    // ---- assignment ----
    mma_gemm<0,0,1,1,256><<<GN, 256, MM_SMEM>>>(pX2, N_NODES, nullptr, nullptr, nullptr,
                                                nullptr, nullptr, pWTA, ab1, pT1);
    {
        dim3 lb(32, 8);
        logits_kernel<<<(N_NODES + 7) / 8, lb>>>(pT1, aw2, ab2, pLG);
    }
    gumbel_kernel<<<80, 256>>>(pLG, u, out_s, pColsum, pEntsum);
    loss_kernel<<<1, 32>>>(pColsum, pEntsum, out_loss);

    // ---- pooling ----
    bounds_kernel<<<1, 32>>>(batch, pBstart);
    {
        dim3 pg(B_BATCH, 8);
        pooled_kernel<<<pg, 256>>>(pX2, out_s, pBstart, pPooled);
    }

    // ---- output MLP ----
    mma_gemm<0,0,1,1,256><<<dim3(4, 2), 256, MM_SMEM>>>(
        pPooled, B_BATCH * S_DIM, nullptr, nullptr, nullptr,
        nullptr, nullptr, pWTO, ob1, pTO);
    out2_kernel<<<B_BATCH * S_DIM, 128>>>(pTO, ow2, ob2, out_latent);
}

// round 6
// speedup vs baseline: 3.0424x; 1.0454x over previous
#include <cuda_runtime.h>
#include <cstdint>

// Problem constants
#define N_NODES 20000
#define N_EDGES 320000
#define F_IN    64
#define H_DIM   256
#define S_DIM   32
#define L_DIM   128
#define B_BATCH 16
#define EPSF    1e-9f

// ===================== helpers =====================
__device__ __forceinline__ uint32_t smem_u32(const void* p) {
    uint32_t a;
    asm("{ .reg .u64 t; cvta.to.shared.u64 t, %1; cvt.u32.u64 %0, t; }" : "=r"(a) : "l"(p));
    return a;
}
__device__ __forceinline__ uint32_t f2tf32(float f) {
    uint32_t r;
    asm("cvt.rna.tf32.f32 %0, %1;" : "=r"(r) : "f"(f));
    return r;
}
__device__ __forceinline__ void mma8(float* c, const uint32_t* a, uint32_t b0, uint32_t b1) {
    asm volatile(
        "mma.sync.aligned.m16n8k8.row.col.f32.tf32.tf32.f32 "
        "{%0,%1,%2,%3}, {%4,%5,%6,%7}, {%8,%9}, {%0,%1,%2,%3};"
        : "+f"(c[0]), "+f"(c[1]), "+f"(c[2]), "+f"(c[3])
        : "r"(a[0]), "r"(a[1]), "r"(a[2]), "r"(a[3]), "r"(b0), "r"(b1));
}
__device__ __forceinline__ void ldsm4(uint32_t* r, uint32_t addr) {
    asm volatile("ldmatrix.sync.aligned.m8n8.x4.shared.b16 {%0,%1,%2,%3}, [%4];"
                 : "=r"(r[0]), "=r"(r[1]), "=r"(r[2]), "=r"(r[3]) : "r"(addr));
}
__device__ __forceinline__ void red2(float* addr, float v0, float v1) {
    asm volatile("red.global.add.v2.f32 [%0], {%1, %2};"
                 :: "l"(addr), "f"(v0), "f"(v1) : "memory");
}

// ===================== device scratch =====================
__device__ float d_XA[N_NODES * H_DIM];
__device__ float d_XB[N_NODES * H_DIM];
__device__ float d_HS1[N_NODES * H_DIM];
__device__ float d_HS2[N_NODES * H_DIM];
__device__ float d_ACC[N_NODES * H_DIM];
__device__ float d_XLN[N_NODES * H_DIM];
__device__ float d_X2[N_NODES * H_DIM];
__device__ float d_T1[N_NODES * H_DIM];
__device__ float d_LG[N_NODES * S_DIM];
__device__ float d_degf[N_NODES];
__device__ float d_pooled[B_BATCH * S_DIM * H_DIM];
__device__ float d_TO[B_BATCH * S_DIM * H_DIM];
__device__ float d_colsum[S_DIM];
__device__ float d_entsum[1];
__device__ int   d_bstart[B_BATCH + 1];
// transposed (and tf32-rounded) weights [N][K]
__device__ float d_WT1a[256 * 64];
__device__ float d_WT1b[256 * 64];
__device__ float d_WT2[256 * 256];
__device__ float d_WT3[256 * 256];
__device__ float d_WT4a[256 * 256];
__device__ float d_WT4b[256 * 256];
__device__ float d_WT5[256 * 256];
__device__ float d_WT6[256 * 256];
__device__ float d_WTA[256 * 256];
__device__ float d_WTO[256 * 256];

// ===================== fused zero =====================
struct ZeroPars { float* p[6]; int n[6]; };
__global__ void zero_all(ZeroPars zp) {
    int r = blockIdx.y;
    float* p = zp.p[r];
    int n = zp.n[r];
    int i = blockIdx.x * blockDim.x + threadIdx.x;
    int st = gridDim.x * blockDim.x;
    for (; i < n; i += st) p[i] = 0.f;
}

__global__ void deg_kernel(const int* __restrict__ dst, float* __restrict__ degf) {
    int i = blockIdx.x * blockDim.x + threadIdx.x;
    int st = gridDim.x * blockDim.x;
    for (; i < N_EDGES; i += st) atomicAdd(&degf[dst[i]], 1.f);
}

// ===================== batched transpose (tf32 round) =====================
struct TransPars { const float* src[10]; float* dst[10]; int R[10]; };
__global__ void transpose_all(TransPars tp) {
    __shared__ float t[32][33];
    int m = blockIdx.z;
    const float* in = tp.src[m];
    float* out = tp.dst[m];
    int R = tp.R[m];
    int c0 = blockIdx.x * 32, r0 = blockIdx.y * 32;
    if (r0 >= R) return;
    for (int j = threadIdx.y; j < 32; j += 8) {
        int r = r0 + j, c = c0 + threadIdx.x;
        t[j][threadIdx.x] = (r < R) ? in[(size_t)r * 256 + c] : 0.f;
    }
    __syncthreads();
    for (int j = threadIdx.y; j < 32; j += 8) {
        int oc = c0 + j, orr = r0 + threadIdx.x;
        if (orr < R)
            out[(size_t)oc * R + orr] = __uint_as_float(f2tf32(t[threadIdx.x][j]));
    }
}

// ===================== tf32 mma.sync GEMM (ldmatrix fragment loads) ==========
// CTA tile 128(M) x 128(N), grid.y picks the 128-col block. K chunks of 32.
// 8 warps: wm = wid&3 (4 x 32 rows), wn = wid>>2 (2 x 64 cols). Warp tile 32x64.
// GATHER: A row = relu(XA[gdst] + XB[gsrc] + bpre), K=256.
// SCATTER: epilogue red.v2 into C[gdst] (bias/relu applied per edge first).
// Smem stride 36 floats (144B): consecutive rows shift 4 banks -> ldmatrix
// 8-address groups hit 32 distinct banks (conflict-free).
#define ASLOT 4608  // 128*36 floats

template<int GATHER, int SCATTER, int RELU_OUT, int ADD_BIAS, int KLEN>
__global__ void __launch_bounds__(256, 2) mma_gemm(
    const float* __restrict__ A, int M,
    const float* __restrict__ XA, const float* __restrict__ XB,
    const float* __restrict__ bpre,
    const int* __restrict__ gsrc, const int* __restrict__ gdst,
    const float* __restrict__ WT,   // [256][KLEN] K-major, tf32-rounded
    const float* __restrict__ bias,
    float* __restrict__ C)
{
    extern __shared__ float sm[];
    float* sA = sm;                    // 2 * ASLOT
    float* sB = sm + 2 * ASLOT;        // 2 * ASLOT
    int* sdst = (int*)(sm + 4 * ASLOT);
    int* ssrc = sdst + 128;

    const int tid  = threadIdx.x;
    const int lane = tid & 31;
    const int wid  = tid >> 5;
    const int wm = wid & 3;
    const int wn = wid >> 2;
    const int lr = lane >> 2;
    const int lc = lane & 3;
    const int row0 = blockIdx.x * 128;
    const int col0 = blockIdx.y * 128;
    constexpr int NCH = KLEN / 32;

    if ((GATHER || SCATTER) && tid < 128) {
        sdst[tid] = gdst[row0 + tid];
        if (GATHER) ssrc[tid] = gsrc[row0 + tid];
    }
    if (GATHER || SCATTER) __syncthreads();

    const int arow = tid >> 1;
    const int akh  = (tid & 1) << 4;
    const int bn   = tid >> 1;
    const int bkh  = (tid & 1) << 4;
    const uint32_t sA_addr = smem_u32(sA);
    const uint32_t sB_addr = smem_u32(sB);
    const float* WTb = WT + (size_t)(col0 + bn) * KLEN + bkh;

    // ldmatrix per-thread base byte offsets (group = lane>>3, rif = lane&7)
    const int grp = lane >> 3;
    const int rif = lane & 7;
    // A tiles order: {rows0-7,k0-3},{rows8-15,k0-3},{rows0-7,k4-7},{rows8-15,k4-7}
    const uint32_t aLdm = sA_addr
        + (uint32_t)(wm * 32 + (grp & 1) * 8 + rif) * 144u + (uint32_t)(grp >> 1) * 16u;
    // B tiles order: {nt,k0-3},{nt,k4-7},{nt+1,k0-3},{nt+1,k4-7}
    const uint32_t bLdm = sB_addr
        + (uint32_t)(wn * 64 + (grp >> 1) * 8 + rif) * 144u + (uint32_t)(grp & 1) * 16u;

    float4 ra[4], rb4[4];

    // ---- B issue (cp.async, 4x16B per thread) ----
#define ISSUE_B(c, buf)                                                          \
    do {                                                                         \
        uint32_t dstb = sB_addr + (uint32_t)((buf) * ASLOT + bn * 36 + bkh) * 4u;\
        const float* srcb = WTb + (c) * 32;                                      \
        _Pragma("unroll")                                                        \
        for (int i = 0; i < 4; i++)                                              \
            asm volatile("cp.async.ca.shared.global [%0], [%1], 16;" ::          \
                         "r"(dstb + (uint32_t)i * 16u), "l"(srcb + i * 4) : "memory"); \
        asm volatile("cp.async.commit_group;" ::: "memory");                     \
    } while (0)

    // ---- A load to regs ----
#define LOAD_A(c)                                                                \
    do {                                                                         \
        int kg = (c) * 32 + akh;                                                 \
        if (GATHER) {                                                            \
            const float* pa = XA + (size_t)sdst[arow] * 256 + kg;                \
            const float* pb = XB + (size_t)ssrc[arow] * 256 + kg;                \
            _Pragma("unroll")                                                    \
            for (int i = 0; i < 4; i++) {                                        \
                ra[i]  = *(const float4*)(pa + 4 * i);                           \
                rb4[i] = *(const float4*)(pb + 4 * i);                           \
            }                                                                    \
        } else {                                                                 \
            int rg = row0 + arow;                                                \
            const float* pa = A + (size_t)rg * KLEN + kg;                        \
            _Pragma("unroll")                                                    \
            for (int i = 0; i < 4; i++)                                          \
                ra[i] = (rg < M) ? *(const float4*)(pa + 4 * i)                  \
                                 : make_float4(0.f, 0.f, 0.f, 0.f);              \
        }                                                                        \
    } while (0)

    // ---- A regs -> smem (relu(XA+XB+b) for gather, tf32 round) ----
#define STS_A(c, buf)                                                            \
    do {                                                                         \
        float* dsta = sA + (buf) * ASLOT + arow * 36 + akh;                      \
        int kg = (c) * 32 + akh;                                                 \
        _Pragma("unroll")                                                        \
        for (int i = 0; i < 4; i++) {                                            \
            float4 v = ra[i];                                                    \
            if (GATHER) {                                                        \
                float4 vb = rb4[i];                                              \
                float4 vc = *(const float4*)(bpre + kg + 4 * i);                 \
                v.x = fmaxf(v.x + vb.x + vc.x, 0.f);                             \
                v.y = fmaxf(v.y + vb.y + vc.y, 0.f);                             \
                v.z = fmaxf(v.z + vb.z + vc.z, 0.f);                             \
                v.w = fmaxf(v.w + vb.w + vc.w, 0.f);                             \
            }                                                                    \
            float4 o;                                                            \
            o.x = __uint_as_float(f2tf32(v.x));                                  \
            o.y = __uint_as_float(f2tf32(v.y));                                  \
            o.z = __uint_as_float(f2tf32(v.z));                                  \
            o.w = __uint_as_float(f2tf32(v.w));                                  \
            *(float4*)(dsta + 4 * i) = o;                                        \
        }                                                                        \
    } while (0)

    float acc[2][8][4];
#pragma unroll
    for (int mt = 0; mt < 2; mt++)
#pragma unroll
        for (int nt = 0; nt < 8; nt++)
#pragma unroll
            for (int j = 0; j < 4; j++) acc[mt][nt][j] = 0.f;

    // prologue
    ISSUE_B(0, 0);
    LOAD_A(0);
    STS_A(0, 0);

#pragma unroll
    for (int c = 0; c < NCH; c++) {
        const int buf = c & 1;
        asm volatile("cp.async.wait_group 0;" ::: "memory");
        __syncthreads();
        if (c + 1 < NCH) {
            ISSUE_B(c + 1, buf ^ 1);
            LOAD_A(c + 1);
        }
        // mma over chunk c (ldmatrix fragment loads)
        const uint32_t aB = aLdm + (uint32_t)(buf * ASLOT * 4);
        const uint32_t bB = bLdm + (uint32_t)(buf * ASLOT * 4);
#pragma unroll
        for (int ks = 0; ks < 4; ks++) {
            uint32_t a0[4], a1[4];
            ldsm4(a0, aB + (uint32_t)ks * 32u);
            ldsm4(a1, aB + 16u * 144u + (uint32_t)ks * 32u);
#pragma unroll
            for (int ntp = 0; ntp < 4; ntp++) {
                uint32_t b[4];
                ldsm4(b, bB + (uint32_t)ntp * 16u * 144u + (uint32_t)ks * 32u);
                mma8(acc[0][2 * ntp + 0], a0, b[0], b[1]);
                mma8(acc[1][2 * ntp + 0], a1, b[0], b[1]);
                mma8(acc[0][2 * ntp + 1], a0, b[2], b[3]);
                mma8(acc[1][2 * ntp + 1], a1, b[2], b[3]);
            }
        }
        if (c + 1 < NCH) STS_A(c + 1, buf ^ 1);
    }

    // ---- epilogue ----
#pragma unroll
    for (int mt = 0; mt < 2; mt++) {
#pragma unroll
        for (int part = 0; part < 2; part++) {
            const int rloc = wm * 32 + mt * 16 + lr + part * 8;
            const int rg = row0 + rloc;
            if (!(GATHER || SCATTER) && rg >= M) continue;
            float* outp = SCATTER ? (C + (size_t)sdst[rloc] * 256)
                                  : (C + (size_t)rg * 256);
#pragma unroll
            for (int nt = 0; nt < 8; nt++) {
                const int col = col0 + wn * 64 + nt * 8 + 2 * lc;
                float v0 = acc[mt][nt][part * 2 + 0];
                float v1 = acc[mt][nt][part * 2 + 1];
                if (ADD_BIAS) { v0 += bias[col]; v1 += bias[col + 1]; }
                if (RELU_OUT) { v0 = fmaxf(v0, 0.f); v1 = fmaxf(v1, 0.f); }
                if (SCATTER) {
                    red2(outp + col, v0, v1);
                } else {
                    *(float2*)(outp + col) = make_float2(v0, v1);
                }
            }
        }
    }
}

static constexpr size_t MM_SMEM = 4u * ASLOT * 4u + 256u * 4u;  // 74752 B

// ---------------- relu + layernorm with deg*b3 pre-add ----------------
__global__ void relu_ln_kernel(const float* __restrict__ IN,
                               const float* __restrict__ degf, const float* __restrict__ b3,
                               const float* __restrict__ g, const float* __restrict__ b,
                               float* __restrict__ OUT)
{
    int gid = blockIdx.x * blockDim.x + threadIdx.x;
    int node = gid >> 5;
    int lane = gid & 31;
    if (node >= N_NODES) return;
    const float* x = &IN[(size_t)node * 256];
    float dg = degf[node];
    float v[8];
    float s = 0.f;
#pragma unroll
    for (int q = 0; q < 2; q++) {
        float4 t = *(const float4*)(&x[lane * 8 + q * 4]);
        float4 bb = *(const float4*)(&b3[lane * 8 + q * 4]);
        v[q * 4 + 0] = fmaxf(fmaf(dg, bb.x, t.x), 0.f);
        v[q * 4 + 1] = fmaxf(fmaf(dg, bb.y, t.y), 0.f);
        v[q * 4 + 2] = fmaxf(fmaf(dg, bb.z, t.z), 0.f);
        v[q * 4 + 3] = fmaxf(fmaf(dg, bb.w, t.w), 0.f);
    }
#pragma unroll
    for (int i = 0; i < 8; i++) s += v[i];
#pragma unroll
    for (int o = 16; o > 0; o >>= 1) s += __shfl_xor_sync(0xffffffffu, s, o);
    float mu = s * (1.f / 256.f);
    float vs = 0.f;
#pragma unroll
    for (int i = 0; i < 8; i++) { float d = v[i] - mu; vs += d * d; }
#pragma unroll
    for (int o = 16; o > 0; o >>= 1) vs += __shfl_xor_sync(0xffffffffu, vs, o);
    float inv = rsqrtf(vs * (1.f / 256.f) + 1e-5f);
#pragma unroll
    for (int i = 0; i < 8; i++) {
        int c = lane * 8 + i;
        OUT[(size_t)node * 256 + c] = (v[i] - mu) * inv * g[c] + b[c];
    }
}

// ---------------- logits = T1 @ aw2 + ab2 (N x 32) ----------------
__global__ void logits_kernel(const float* __restrict__ T1, const float* __restrict__ aw2,
                              const float* __restrict__ ab2, float* __restrict__ LG)
{
    int c = threadIdx.x;
    int n = blockIdx.x * blockDim.y + threadIdx.y;
    if (n >= N_NODES) return;
    const float* t = &T1[(size_t)n * 256];
    float acc = ab2[c];
#pragma unroll 8
    for (int k = 0; k < 256; k++) acc = fmaf(t[k], aw2[k * 32 + c], acc);
    LG[n * 32 + c] = acc;
}

// ---------------- gumbel softmax + loss partials ----------------
__global__ void gumbel_kernel(const float* __restrict__ LG, const float* __restrict__ U,
                              float* __restrict__ sOut, float* __restrict__ colsum,
                              float* __restrict__ entsum)
{
    int lane = threadIdx.x & 31;
    int gw = (blockIdx.x * blockDim.x + threadIdx.x) >> 5;
    int nw = (gridDim.x * blockDim.x) >> 5;
    float colAcc = 0.f, entAcc = 0.f;
    for (int n = gw; n < N_NODES; n += nw) {
        float u = U[n * 32 + lane];
        float gn = -logf(-logf(u + EPSF) + EPSF);
        float v = LG[n * 32 + lane] + gn;
        float mx = v;
#pragma unroll
        for (int o = 16; o > 0; o >>= 1) mx = fmaxf(mx, __shfl_xor_sync(0xffffffffu, mx, o));
        float e = expf(v - mx);
        float ssum = e;
#pragma unroll
        for (int o = 16; o > 0; o >>= 1) ssum += __shfl_xor_sync(0xffffffffu, ssum, o);
        float sv = e / ssum;
        sOut[n * 32 + lane] = sv;
        colAcc += sv;
        entAcc += sv * logf(sv + EPSF);
    }
    atomicAdd(&colsum[lane], colAcc);
#pragma unroll
    for (int o = 16; o > 0; o >>= 1) entAcc += __shfl_xor_sync(0xffffffffu, entAcc, o);
    if (lane == 0) atomicAdd(entsum, entAcc);
}

__global__ void loss_kernel(const float* __restrict__ colsum, const float* __restrict__ entsum,
                            float* __restrict__ outLoss)
{
    int lane = threadIdx.x;
    float avg = colsum[lane] * (1.f / (float)N_NODES);
    float dv = avg * logf(avg + EPSF);
#pragma unroll
    for (int o = 16; o > 0; o >>= 1) dv += __shfl_xor_sync(0xffffffffu, dv, o);
    if (lane == 0) outLoss[0] = dv - entsum[0] * (1.f / (float)N_NODES);
}

__global__ void bounds_kernel(const int* __restrict__ batch, int* __restrict__ bstart)
{
    int t = threadIdx.x;
    if (t > B_BATCH) return;
    int lo = 0, hi = N_NODES;
    while (lo < hi) {
        int mid = (lo + hi) >> 1;
        if (batch[mid] < t) lo = mid + 1; else hi = mid;
    }
    bstart[t] = lo;
}

__global__ void pooled_kernel(const float* __restrict__ X2, const float* __restrict__ S,
                              const int* __restrict__ bstart, float* __restrict__ pooled)
{
    int b = blockIdx.x;
    int nchunk = gridDim.y;
    int s0 = bstart[b], s1 = bstart[b + 1];
    int len = s1 - s0;
    int per = (len + nchunk - 1) / nchunk;
    int n0 = s0 + blockIdx.y * per;
    int n1 = min(n0 + per, s1);
    if (n0 >= n1) return;

    int h = threadIdx.x;
    float acc[32];
#pragma unroll
    for (int k = 0; k < 32; k++) acc[k] = 0.f;

    __shared__ float st[8][33];
    for (int basei = n0; basei < n1; basei += 8) {
        __syncthreads();
        {
            int rr = threadIdx.x >> 5, cc = threadIdx.x & 31;
            st[rr][cc] = (basei + rr < n1) ? S[(size_t)(basei + rr) * 32 + cc] : 0.f;
        }
        __syncthreads();
        int cnt = min(8, n1 - basei);
        for (int rr = 0; rr < cnt; rr++) {
            float xv = X2[(size_t)(basei + rr) * 256 + h];
#pragma unroll
            for (int k = 0; k < 32; k++) acc[k] = fmaf(st[rr][k], xv, acc[k]);
        }
    }
#pragma unroll
    for (int k = 0; k < 32; k++)
        atomicAdd(&pooled[((size_t)b * 32 + k) * 256 + h], acc[k]);
}

__global__ void out2_kernel(const float* __restrict__ TO, const float* __restrict__ ow2,
                            const float* __restrict__ ob2, float* __restrict__ out)
{
    int r = blockIdx.x;
    int c = threadIdx.x;
    const float* t = &TO[(size_t)r * 256];
    float acc = ob2[c];
#pragma unroll 8
    for (int k = 0; k < 256; k++) acc = fmaf(t[k], ow2[k * 128 + c], acc);
    out[(size_t)r * 128 + c] = acc;
}

// ===================== launch =====================
extern "C" void kernel_launch(void* const* d_in, const int* in_sizes, int n_in,
                              void* d_out, int out_size)
{
    const float* x    = (const float*)d_in[0];
    const float* u    = (const float*)d_in[1];
    const int*   ei   = (const int*)d_in[2];
    const int*   batch= (const int*)d_in[3];
    const float* g1w1 = (const float*)d_in[4];
    const float* g1b1 = (const float*)d_in[5];
    const float* g1w2 = (const float*)d_in[6];
    const float* g1b2 = (const float*)d_in[7];
    const float* g1w3 = (const float*)d_in[8];
    const float* g1b3 = (const float*)d_in[9];
    const float* ln1g = (const float*)d_in[10];
    const float* ln1b = (const float*)d_in[11];
    const float* g2w1 = (const float*)d_in[12];
    const float* g2b1 = (const float*)d_in[13];
    const float* g2w2 = (const float*)d_in[14];
    const float* g2b2 = (const float*)d_in[15];
    const float* g2w3 = (const float*)d_in[16];
    const float* g2b3 = (const float*)d_in[17];
    const float* ln2g = (const float*)d_in[18];
    const float* ln2b = (const float*)d_in[19];
    const float* aw1  = (const float*)d_in[20];
    const float* ab1  = (const float*)d_in[21];
    const float* aw2  = (const float*)d_in[22];
    const float* ab2  = (const float*)d_in[23];
    const float* ow1  = (const float*)d_in[24];
    const float* ob1  = (const float*)d_in[25];
    const float* ow2  = (const float*)d_in[26];
    const float* ob2  = (const float*)d_in[27];

    const int* srcI = ei;
    const int* dstI = ei + N_EDGES;

    float* out        = (float*)d_out;
    float* out_latent = out;
    float* out_s      = out + B_BATCH * S_DIM * L_DIM;
    float* out_loss   = out_s + (size_t)N_NODES * S_DIM;

    float *pXA, *pXB, *pHS1, *pHS2, *pACC, *pXLN, *pX2, *pT1, *pLG, *pDeg, *pPooled, *pTO, *pColsum, *pEntsum;
    float *pWT1a, *pWT1b, *pWT2, *pWT3, *pWT4a, *pWT4b, *pWT5, *pWT6, *pWTA, *pWTO;
    int* pBstart;
    cudaGetSymbolAddress((void**)&pXA, d_XA);
    cudaGetSymbolAddress((void**)&pXB, d_XB);
    cudaGetSymbolAddress((void**)&pHS1, d_HS1);
    cudaGetSymbolAddress((void**)&pHS2, d_HS2);
    cudaGetSymbolAddress((void**)&pACC, d_ACC);
    cudaGetSymbolAddress((void**)&pXLN, d_XLN);
    cudaGetSymbolAddress((void**)&pX2, d_X2);
    cudaGetSymbolAddress((void**)&pT1, d_T1);
    cudaGetSymbolAddress((void**)&pLG, d_LG);
    cudaGetSymbolAddress((void**)&pDeg, d_degf);
    cudaGetSymbolAddress((void**)&pPooled, d_pooled);
    cudaGetSymbolAddress((void**)&pTO, d_TO);
    cudaGetSymbolAddress((void**)&pColsum, d_colsum);
    cudaGetSymbolAddress((void**)&pEntsum, d_entsum);
    cudaGetSymbolAddress((void**)&pBstart, d_bstart);
    cudaGetSymbolAddress((void**)&pWT1a, d_WT1a);
    cudaGetSymbolAddress((void**)&pWT1b, d_WT1b);
    cudaGetSymbolAddress((void**)&pWT2, d_WT2);
    cudaGetSymbolAddress((void**)&pWT3, d_WT3);
    cudaGetSymbolAddress((void**)&pWT4a, d_WT4a);
    cudaGetSymbolAddress((void**)&pWT4b, d_WT4b);
    cudaGetSymbolAddress((void**)&pWT5, d_WT5);
    cudaGetSymbolAddress((void**)&pWT6, d_WT6);
    cudaGetSymbolAddress((void**)&pWTA, d_WTA);
    cudaGetSymbolAddress((void**)&pWTO, d_WTO);

    cudaFuncSetAttribute(mma_gemm<0,0,0,0,64>,  cudaFuncAttributeMaxDynamicSharedMemorySize, (int)MM_SMEM);
    cudaFuncSetAttribute(mma_gemm<1,1,1,1,256>, cudaFuncAttributeMaxDynamicSharedMemorySize, (int)MM_SMEM);
    cudaFuncSetAttribute(mma_gemm<0,0,0,0,256>, cudaFuncAttributeMaxDynamicSharedMemorySize, (int)MM_SMEM);
    cudaFuncSetAttribute(mma_gemm<0,0,1,1,256>, cudaFuncAttributeMaxDynamicSharedMemorySize, (int)MM_SMEM);

    const dim3 GN((N_NODES + 127) / 128, 2);   // 157 x 2
    const dim3 GE(N_EDGES / 128, 2);           // 2500 x 2

    // ---- fused zeroing + degree + all weight transposes ----
    {
        ZeroPars zp;
        zp.p[0] = pHS1;    zp.n[0] = N_NODES * H_DIM;
        zp.p[1] = pHS2;    zp.n[1] = N_NODES * H_DIM;
        zp.p[2] = pDeg;    zp.n[2] = N_NODES;
        zp.p[3] = pColsum; zp.n[3] = S_DIM;
        zp.p[4] = pEntsum; zp.n[4] = 1;
        zp.p[5] = pPooled; zp.n[5] = B_BATCH * S_DIM * H_DIM;
        zero_all<<<dim3(160, 6), 256>>>(zp);
    }
    deg_kernel<<<256, 256>>>(dstI, pDeg);
    {
        TransPars tp;
        tp.src[0] = g1w1;             tp.dst[0] = pWT1a; tp.R[0] = 64;
        tp.src[1] = g1w1 + 64 * 256;  tp.dst[1] = pWT1b; tp.R[1] = 64;
        tp.src[2] = g1w2;             tp.dst[2] = pWT2;  tp.R[2] = 256;
        tp.src[3] = g1w3;             tp.dst[3] = pWT3;  tp.R[3] = 256;
        tp.src[4] = g2w1;             tp.dst[4] = pWT4a; tp.R[4] = 256;
        tp.src[5] = g2w1 + 256 * 256; tp.dst[5] = pWT4b; tp.R[5] = 256;
        tp.src[6] = g2w2;             tp.dst[6] = pWT5;  tp.R[6] = 256;
        tp.src[7] = g2w3;             tp.dst[7] = pWT6;  tp.R[7] = 256;
        tp.src[8] = aw1;              tp.dst[8] = pWTA;  tp.R[8] = 256;
        tp.src[9] = ow1;              tp.dst[9] = pWTO;  tp.R[9] = 256;
        dim3 tg(8, 8, 10), tb(32, 8);
        transpose_all<<<tg, tb>>>(tp);
    }

    // ---- layer 1 ----
    mma_gemm<0,0,0,0,64><<<GN, 256, MM_SMEM>>>(x, N_NODES, nullptr, nullptr, nullptr,
                                               nullptr, nullptr, pWT1a, nullptr, pXA);
    mma_gemm<0,0,0,0,64><<<GN, 256, MM_SMEM>>>(x, N_NODES, nullptr, nullptr, nullptr,
                                               nullptr, nullptr, pWT1b, nullptr, pXB);
    mma_gemm<1,1,1,1,256><<<GE, 256, MM_SMEM>>>(nullptr, N_EDGES, pXA, pXB, g1b1,
                                                srcI, dstI, pWT2, g1b2, pHS1);
    mma_gemm<0,0,0,0,256><<<GN, 256, MM_SMEM>>>(pHS1, N_NODES, nullptr, nullptr, nullptr,
                                                nullptr, nullptr, pWT3, nullptr, pACC);
    relu_ln_kernel<<<(N_NODES * 32 + 255) / 256, 256>>>(pACC, pDeg, g1b3, ln1g, ln1b, pXLN);

    // ---- layer 2 ----
    mma_gemm<0,0,0,0,256><<<GN, 256, MM_SMEM>>>(pXLN, N_NODES, nullptr, nullptr, nullptr,
                                                nullptr, nullptr, pWT4a, nullptr, pXA);
    mma_gemm<0,0,0,0,256><<<GN, 256, MM_SMEM>>>(pXLN, N_NODES, nullptr, nullptr, nullptr,
                                                nullptr, nullptr, pWT4b, nullptr, pXB);
    mma_gemm<1,1,1,1,256><<<GE, 256, MM_SMEM>>>(nullptr, N_EDGES, pXA, pXB, g2b1,
                                                srcI, dstI, pWT5, g2b2, pHS2);
    mma_gemm<0,0,0,0,256><<<GN, 256, MM_SMEM>>>(pHS2, N_NODES, nullptr, nullptr, nullptr,
                                                nullptr, nullptr, pWT6, nullptr, pACC);
    relu_ln_kernel<<<(N_NODES * 32 + 255) / 256, 256>>>(pACC, pDeg, g2b3, ln2g, ln2b, pX2);

    // ---- assignment ----
    mma_gemm<0,0,1,1,256><<<GN, 256, MM_SMEM>>>(pX2, N_NODES, nullptr, nullptr, nullptr,
                                                nullptr, nullptr, pWTA, ab1, pT1);
    {
        dim3 lb(32, 8);
        logits_kernel<<<(N_NODES + 7) / 8, lb>>>(pT1, aw2, ab2, pLG);
    }
    gumbel_kernel<<<80, 256>>>(pLG, u, out_s, pColsum, pEntsum);
    loss_kernel<<<1, 32>>>(pColsum, pEntsum, out_loss);

    // ---- pooling ----
    bounds_kernel<<<1, 32>>>(batch, pBstart);
    {
        dim3 pg(B_BATCH, 8);
        pooled_kernel<<<pg, 256>>>(pX2, out_s, pBstart, pPooled);
    }

    // ---- output MLP ----
    mma_gemm<0,0,1,1,256><<<dim3(4, 2), 256, MM_SMEM>>>(
        pPooled, B_BATCH * S_DIM, nullptr, nullptr, nullptr,
        nullptr, nullptr, pWTO, ob1, pTO);
    out2_kernel<<<B_BATCH * S_DIM, 128>>>(pTO, ow2, ob2, out_latent);
}